// round 1
// baseline (speedup 1.0000x reference)
#include <cuda_runtime.h>
#include <stdint.h>
#include <math.h>

// ---------------------------------------------------------------------------
// ConvLSTMBlock: x(4,16,128,128,32) --conv W(3,3,32,256),s2,SAME--> xz(64,64,64,256)
// 16-step LSTM: z = xz[t] + conv(h, U(3,3,64,256), s1, SAME) + b
//   i,f,g,o = split(z); i,f,o = hard_sigmoid; c = f*c + i*tanh(g); h = o*tanh(c)
// out(4,16,64,64,64) = (h - mean) * gamma/sqrt(var+eps) + beta
// ---------------------------------------------------------------------------

// Scratch (device globals: allocation-free rule)
__device__ float g_xz[(size_t)64 * 4096 * 256]; // (b*16+t, px, 256)
__device__ float g_z [(size_t)4  * 4096 * 256]; // (b, px, 256)
__device__ float g_h [(size_t)4  * 4096 * 64];
__device__ float g_c [(size_t)4  * 4096 * 64];

__device__ __forceinline__ unsigned long long pack2(float v) {
    unsigned long long r;
    asm("mov.b64 %0, {%1, %1};" : "=l"(r) : "f"(v));
    return r;
}
__device__ __forceinline__ unsigned long long fma2(unsigned long long a,
                                                   unsigned long long b,
                                                   unsigned long long c) {
    unsigned long long d;
    asm("fma.rn.f32x2 %0, %1, %2, %3;" : "=l"(d) : "l"(a), "l"(b), "l"(c));
    return d;
}
__device__ __forceinline__ float2 unpack2(unsigned long long p) {
    float2 r;
    asm("mov.b64 {%0, %1}, %2;" : "=f"(r.x), "=f"(r.y) : "l"(p));
    return r;
}

// Direct conv, 3x3, SAME. Block: 8x8 output pixels x 64 output channels.
// Threads 256: tx = channel-quad (16), ty = pixel-quad (16) -> 4px x 4ch each.
// smem: input patch channel-major (odd plane stride, conflict-free) + weight
// chunk [9*32 rows][64 ch].
template <int STRIDE, int CIN, bool REC>
__global__ void __launch_bounds__(256, 2) conv_kernel(
    const float* __restrict__ src,   // input conv: x ; recurrent: unused (reads g_h)
    const float* __restrict__ wgt,   // (3,3,CIN,256) HWIO
    const float* __restrict__ bias,  // (256) for REC
    int t)
{
    constexpr int IN    = REC ? 64 : 128;
    constexpr int PATCH = (8 - 1) * STRIDE + 3;     // 17 (s2) / 10 (s1)
    constexpr int PLANE = (PATCH * PATCH) | 1;      // 289 / 101 (odd -> no bank conflicts)
    constexpr int PAD   = REC ? 1 : 0;              // SAME: s2 pad_lo=0, s1 pad_lo=1
    constexpr int CSH   = (CIN == 32) ? 5 : 6;

    extern __shared__ float smem[];
    float* patch = smem;
    float* wsm   = smem + CIN * PLANE;

    const int tid  = threadIdx.x;
    const int tx   = tid & 15;        // channel quad
    const int ty   = tid >> 4;        // pixel quad
    const int r    = ty >> 1;         // out row in tile (0..7)
    const int c0   = (ty & 1) * 4;    // out col base (0 or 4)
    const int tileY = blockIdx.x >> 3, tileX = blockIdx.x & 7;
    const int img  = blockIdx.y;      // input conv: 0..63 (b*16+t) ; rec: b 0..3
    const int co0  = blockIdx.z * 64;
    const int y0   = tileY * 8 * STRIDE - PAD;
    const int x0   = tileX * 8 * STRIDE - PAD;

    // ---- stage input patch (zero-filled OOB), channel-major ----
    const float* sp;
    if (REC) sp = g_h + (size_t)img * IN * IN * CIN;
    else     sp = src + (size_t)img * IN * IN * CIN;

    for (int idx = tid; idx < PATCH * PATCH * CIN; idx += 256) {
        int ci  = idx & (CIN - 1);
        int p   = idx >> CSH;
        int py  = p / PATCH;
        int pxl = p - py * PATCH;
        int iy  = y0 + py, ix = x0 + pxl;
        float v = 0.0f;
        if ((unsigned)iy < (unsigned)IN && (unsigned)ix < (unsigned)IN)
            v = sp[((size_t)iy * IN + ix) * CIN + ci];
        patch[ci * PLANE + py * PATCH + pxl] = v;
    }

    unsigned long long acc[4][2];
#pragma unroll
    for (int p = 0; p < 4; p++) { acc[p][0] = 0ull; acc[p][1] = 0ull; }

    const int pbase = (r * STRIDE) * PATCH + c0 * STRIDE;

    for (int cc = 0; cc < CIN; cc += 32) {
        if (cc) __syncthreads();
        // ---- stage weight chunk: rows kk*32+cil, 64 channels each ----
        for (int idx = tid; idx < 288 * 64; idx += 256) {
            int ch  = idx & 63;
            int row = idx >> 6;
            int kk  = row >> 5, cil = row & 31;
            wsm[idx] = wgt[((size_t)(kk * CIN + cc + cil)) * 256 + co0 + ch];
        }
        __syncthreads();

#pragma unroll
        for (int kk = 0; kk < 9; kk++) {
            const int ky = kk / 3, kx = kk - ky * 3;
            const float* pr0 = patch + cc * PLANE + pbase + ky * PATCH + kx;
            const float* wr0 = wsm + kk * 32 * 64 + tx * 4;
#pragma unroll 4
            for (int cil = 0; cil < 32; cil++) {
                ulonglong2 w = *reinterpret_cast<const ulonglong2*>(wr0 + cil * 64);
                const float* pr = pr0 + cil * PLANE;
#pragma unroll
                for (int p = 0; p < 4; p++) {
                    unsigned long long vv = pack2(pr[p * STRIDE]);
                    acc[p][0] = fma2(w.x, vv, acc[p][0]);
                    acc[p][1] = fma2(w.y, vv, acc[p][1]);
                }
            }
        }
    }

    // ---- epilogue ----
    const int oy = tileY * 8 + r;
    const int ox = tileX * 8 + c0;
    const int px = oy * 64 + ox;

    if (!REC) {
        float* dst = g_xz + ((size_t)img * 4096 + px) * 256 + co0 + tx * 4;
#pragma unroll
        for (int p = 0; p < 4; p++) {
            float2 a = unpack2(acc[p][0]);
            float2 b2 = unpack2(acc[p][1]);
            *reinterpret_cast<float4*>(dst + (size_t)p * 256) =
                make_float4(a.x, a.y, b2.x, b2.y);
        }
    } else {
        const int ch = co0 + tx * 4;
        const float4 bb = *reinterpret_cast<const float4*>(bias + ch);
        const float* xz = g_xz + (((size_t)img * 16 + t) * 4096 + px) * 256 + ch;
        float* dst = g_z + ((size_t)img * 4096 + px) * 256 + ch;
#pragma unroll
        for (int p = 0; p < 4; p++) {
            float2 a = unpack2(acc[p][0]);
            float2 b2 = unpack2(acc[p][1]);
            float4 xzv = *reinterpret_cast<const float4*>(xz + (size_t)p * 256);
            *reinterpret_cast<float4*>(dst + (size_t)p * 256) =
                make_float4(a.x + xzv.x + bb.x, a.y + xzv.y + bb.y,
                            b2.x + xzv.z + bb.z, b2.y + xzv.w + bb.w);
        }
    }
}

__global__ void zero_state_kernel() {
    int i = blockIdx.x * blockDim.x + threadIdx.x;
    if (i < 4 * 4096 * 64) { g_h[i] = 0.0f; g_c[i] = 0.0f; }
}

__global__ void lstm_pointwise_kernel(
    float* __restrict__ out,
    const float* __restrict__ gamma, const float* __restrict__ beta,
    const float* __restrict__ mean,  const float* __restrict__ var,
    int t)
{
    int idx = blockIdx.x * 256 + threadIdx.x;   // 4*4096*64 = 1048576 threads
    int f  = idx & 63;
    int bp = idx >> 6;                          // b*4096 + px
    size_t zb = (size_t)bp * 256 + f;
    float zi = g_z[zb      ];
    float zf = g_z[zb +  64];
    float zg = g_z[zb + 128];
    float zo = g_z[zb + 192];
    float ig = __saturatef(0.2f * zi + 0.5f);
    float fg = __saturatef(0.2f * zf + 0.5f);
    float og = __saturatef(0.2f * zo + 0.5f);
    float cn = fg * g_c[idx] + ig * tanhf(zg);
    float hn = og * tanhf(cn);
    g_c[idx] = cn;
    g_h[idx] = hn;
    int b  = idx >> 18;
    int px = bp & 4095;
    float sc = gamma[f] * rsqrtf(var[f] + 1e-3f);
    out[(((size_t)b * 16 + t) * 4096 + px) * 64 + f] = (hn - mean[f]) * sc + beta[f];
}

extern "C" void kernel_launch(void* const* d_in, const int* in_sizes, int n_in,
                              void* d_out, int out_size)
{
    const float* x     = (const float*)d_in[0];
    const float* W     = (const float*)d_in[1];
    const float* U     = (const float*)d_in[2];
    const float* b     = (const float*)d_in[3];
    const float* gamma = (const float*)d_in[4];
    const float* beta  = (const float*)d_in[5];
    const float* mean  = (const float*)d_in[6];
    const float* var   = (const float*)d_in[7];
    float* out = (float*)d_out;

    const size_t smem_in  = (size_t)(32 * 289 + 288 * 64) * 4;  // 110,720 B
    const size_t smem_rec = (size_t)(64 * 101 + 288 * 64) * 4;  //  99,584 B

    cudaFuncSetAttribute((const void*)conv_kernel<2, 32, false>,
                         cudaFuncAttributeMaxDynamicSharedMemorySize, (int)smem_in);
    cudaFuncSetAttribute((const void*)conv_kernel<1, 64, true>,
                         cudaFuncAttributeMaxDynamicSharedMemorySize, (int)smem_rec);

    zero_state_kernel<<<2048, 512>>>();

    // Input conv for all 64 images: grid(tiles=64, imgs=64, co-chunks=4)
    conv_kernel<2, 32, false><<<dim3(64, 64, 4), 256, smem_in>>>(x, W, nullptr, 0);

    for (int t = 0; t < 16; t++) {
        conv_kernel<1, 64, true><<<dim3(64, 4, 4), 256, smem_rec>>>(nullptr, U, b, t);
        lstm_pointwise_kernel<<<4096, 256>>>(out, gamma, beta, mean, var, t);
    }
}

// round 6
// speedup vs baseline: 3.2507x; 3.2507x over previous
#include <cuda_runtime.h>
#include <cuda_fp16.h>
#include <stdint.h>
#include <math.h>

// ---------------------------------------------------------------------------
// ConvLSTMBlock via ldmatrix + mma.sync (HMMA, arch-neutral PTX: the harness
// compiles PTX at .target sm_103 (no 'a'), so tcgen05/TMEM are unavailable).
//   input conv : GEMM M=262144, N=256, K=288(pad 320), A = im2col(x) stride2
//   recurrent  : GEMM M=16384,  N=256, K=576,          A = im2col(h) stride1
// fp16 2-term split on weights: D = Ah*Bh + Ah*Bl  (fp32 accum).
// Recurrent kernel fuses the full LSTM pointwise + BN into its epilogue.
// ---------------------------------------------------------------------------

// ---- device scratch (allocation-free rule) ----
__device__ __align__(1024) float  g_xz[(size_t)64 * 4096 * 256];
__device__ __align__(1024) float  g_c [(size_t)4  * 4096 * 64];
__device__ __align__(1024) __half g_hf[(size_t)4  * 4096 * 64];
__device__ __align__(1024) __half g_xh[(size_t)64 * 128 * 128 * 32];
__device__ __align__(1024) __half g_UH[256 * 576], g_UL[256 * 576];
__device__ __align__(1024) __half g_WH[256 * 320], g_WL[256 * 320];

// ---- PTX helpers ----
__device__ __forceinline__ uint32_t s2u(const void* p) {
    uint32_t a;
    asm("{ .reg .u64 t; cvta.to.shared.u64 t, %1; cvt.u32.u64 %0, t; }"
        : "=r"(a) : "l"(p));
    return a;
}
__device__ __forceinline__ void cpa16(uint32_t dst, const void* src, uint32_t sz) {
    asm volatile("cp.async.cg.shared.global [%0], [%1], 16, %2;"
                 :: "r"(dst), "l"(src), "r"(sz));
}
__device__ __forceinline__ void cpcommit() {
    asm volatile("cp.async.commit_group;" ::: "memory");
}
template <int N> __device__ __forceinline__ void cpwait() {
    asm volatile("cp.async.wait_group %0;" :: "n"(N) : "memory");
}
__device__ __forceinline__ void ldm4(uint32_t* r, uint32_t addr) {
    asm volatile("ldmatrix.sync.aligned.m8n8.x4.shared.b16 {%0,%1,%2,%3}, [%4];"
                 : "=r"(r[0]), "=r"(r[1]), "=r"(r[2]), "=r"(r[3]) : "r"(addr));
}
__device__ __forceinline__ void mma16816(float* d, const uint32_t* a,
                                         uint32_t b0, uint32_t b1) {
    asm volatile(
        "mma.sync.aligned.m16n8k16.row.col.f32.f16.f16.f32 "
        "{%0,%1,%2,%3}, {%4,%5,%6,%7}, {%8,%9}, {%0,%1,%2,%3};"
        : "+f"(d[0]), "+f"(d[1]), "+f"(d[2]), "+f"(d[3])
        : "r"(a[0]), "r"(a[1]), "r"(a[2]), "r"(a[3]), "r"(b0), "r"(b1));
}

// ---- prep kernels ----
__global__ void prep_weights(const float* __restrict__ W, const float* __restrict__ U) {
    int idx = blockIdx.x * 256 + threadIdx.x;
    const int NU = 256 * 576;
    if (idx < NU) {
        int n = idx / 576, col = idx - n * 576;
        float v = U[(size_t)col * 256 + n];
        __half h = __float2half_rn(v);
        g_UH[idx] = h;
        g_UL[idx] = __float2half_rn(v - __half2float(h));
    } else {
        int j = idx - NU;
        if (j >= 256 * 320) return;
        int n = j / 320, col = j - n * 320;
        float v = (col < 288) ? W[(size_t)col * 256 + n] : 0.0f;
        __half h = __float2half_rn(v);
        g_WH[j] = h;
        g_WL[j] = __float2half_rn(v - __half2float(h));
    }
}

__global__ void x_convert(const float* __restrict__ x) {
    size_t i = (size_t)blockIdx.x * 256 + threadIdx.x;
    if (i >= (size_t)64 * 128 * 128 * 32) return;
    g_xh[i] = __float2half_rn(x[i]);
}

__global__ void zero_state() {
    int i = blockIdx.x * 256 + threadIdx.x;   // 4096 blocks * 256
    g_c[i] = 0.0f;
    g_hf[i] = __half(0.0f);
}

// ---------------------------------------------------------------------------
// GEMM conv. CTA: 128 rows (pixels) x 256 cols (all 4F). 8 warps = 2M x 4N,
// warp tile 64x64. K-chunk 64 (4 k16 steps). Smem: A stage 16KB + B stage
// (Bh 32KB + Bl 32KB), double-buffered = 160KB. XOR-16B swizzle.
// REC==1 fuses LSTM pointwise + BN epilogue.
// ---------------------------------------------------------------------------
template <int REC>
__global__ void __launch_bounds__(256, 1) gemm_conv(
    float* __restrict__ out, const float* __restrict__ bias,
    const float* __restrict__ gamma, const float* __restrict__ beta,
    const float* __restrict__ mean, const float* __restrict__ var, int t)
{
    constexpr int CIN    = REC ? 64 : 32;
    constexpr int CSH    = REC ? 6 : 5;
    constexpr int IN     = REC ? 64 : 128;
    constexpr int STRIDE = REC ? 1 : 2;
    constexpr int PADLO  = REC ? 1 : 0;
    constexpr int NCHUNK = REC ? 9 : 5;
    constexpr int KP     = REC ? 576 : 320;

    const __half* __restrict__ Asrc = REC ? g_hf : g_xh;
    const __half* __restrict__ Bh   = REC ? g_UH : g_WH;
    const __half* __restrict__ Bl   = REC ? g_UL : g_WL;

    extern __shared__ char dsm[];
    const uint32_t smA = s2u(dsm);            // A stages: 2 x 16384
    const uint32_t smB = smA + 32768;         // B stages: 2 x 65536 (Bh, Bl)

    const int tid  = threadIdx.x;
    const int warp = tid >> 5;
    const int L    = tid & 31;
    const int tile = blockIdx.x;
    const int wm   = (warp >> 2) * 64;
    const int wn   = (warp & 3) * 64;

    // ldmatrix per-lane geometry: sub-matrix = L/8
    const int sub  = L >> 3;
    const int ri16 = ((sub & 1) << 3) + (L & 7);  // row within 16
    const int us   = sub >> 1;                    // k-unit select (0/1)

    int aRowB[4], aRM[4], bRowB[4], bRM[4];
#pragma unroll
    for (int mi = 0; mi < 4; mi++) {
        int r = wm + mi * 16 + ri16;
        aRowB[mi] = r * 128; aRM[mi] = r & 7;
    }
#pragma unroll
    for (int jj = 0; jj < 4; jj++) {
        int n = wn + jj * 16 + ri16;
        bRowB[jj] = n * 128; bRM[jj] = n & 7;
    }

    float d[4][8][4];
#pragma unroll
    for (int mi = 0; mi < 4; mi++)
#pragma unroll
        for (int n8 = 0; n8 < 8; n8++)
#pragma unroll
            for (int k = 0; k < 4; k++) d[mi][n8][k] = 0.0f;

    auto load_chunk = [&](int c, int s) {
        uint32_t sa = smA + (uint32_t)s * 16384u;
        uint32_t sb = smB + (uint32_t)s * 65536u;
#pragma unroll
        for (int j = 0; j < 4; j++) {               // A: 1024 16B units
            int i = tid + j * 256;
            int r = i >> 3, q = i & 7;
            int row = tile * 128 + r;
            int img = row >> 12, px = row & 4095, y = px >> 6, x = px & 63;
            int k = c * 64 + q * 8;
            int kpos = k >> CSH;
            int ci0 = k & (CIN - 1);
            int ky = (kpos >= 6) ? 2 : ((kpos >= 3) ? 1 : 0);
            int kx = kpos - 3 * ky;
            int sy = y * STRIDE + ky - PADLO;
            int sx = x * STRIDE + kx - PADLO;
            bool ok = (kpos < 9) && ((unsigned)sy < (unsigned)IN) &&
                      ((unsigned)sx < (unsigned)IN);
            size_t so = ok ? ((((size_t)img * IN + sy) * IN + sx) * CIN + ci0) : 0;
            uint32_t dst = sa + (uint32_t)(r * 128 + ((q ^ (r & 7)) << 4));
            cpa16(dst, Asrc + so, ok ? 16u : 0u);
        }
#pragma unroll
        for (int j = 0; j < 8; j++) {               // B: 2048 16B units (h+l)
            int i = tid + j * 256;
            int n = i >> 3, q = i & 7;
            size_t so = (size_t)n * KP + c * 64 + q * 8;
            uint32_t dd = (uint32_t)(n * 128 + ((q ^ (n & 7)) << 4));
            cpa16(sb + dd, Bh + so, 16u);
            cpa16(sb + 32768u + dd, Bl + so, 16u);
        }
        cpcommit();
    };

    load_chunk(0, 0);

#pragma unroll 1
    for (int c = 0; c < NCHUNK; c++) {
        int s = c & 1;
        if (c + 1 < NCHUNK) { load_chunk(c + 1, s ^ 1); cpwait<1>(); }
        else                { cpwait<0>(); }
        __syncthreads();

        uint32_t sa = smA + (uint32_t)s * 16384u;
        uint32_t sb = smB + (uint32_t)s * 65536u;
#pragma unroll
        for (int kk = 0; kk < 4; kk++) {
            uint32_t a[4][4];
#pragma unroll
            for (int mi = 0; mi < 4; mi++)
                ldm4(a[mi], sa + aRowB[mi] + ((((kk << 1) | us) ^ aRM[mi]) << 4));
#pragma unroll
            for (int jj = 0; jj < 4; jj++) {
                uint32_t baddr = bRowB[jj] + ((((kk << 1) | us) ^ bRM[jj]) << 4);
                uint32_t b[4];
                ldm4(b, sb + baddr);                  // Bh
#pragma unroll
                for (int mi = 0; mi < 4; mi++) {
                    mma16816(d[mi][2 * jj],     a[mi], b[0], b[2]);
                    mma16816(d[mi][2 * jj + 1], a[mi], b[1], b[3]);
                }
                ldm4(b, sb + 32768u + baddr);         // Bl
#pragma unroll
                for (int mi = 0; mi < 4; mi++) {
                    mma16816(d[mi][2 * jj],     a[mi], b[0], b[2]);
                    mma16816(d[mi][2 * jj + 1], a[mi], b[1], b[3]);
                }
            }
        }
        __syncthreads();
    }

    if (!REC) {
        // Plain epilogue: store to g_xz fp32 [row][256]
#pragma unroll
        for (int mi = 0; mi < 4; mi++) {
            int r0 = tile * 128 + wm + mi * 16 + (L >> 2);
#pragma unroll
            for (int n8 = 0; n8 < 8; n8++) {
                int col = wn + n8 * 8 + ((L & 3) << 1);
                *reinterpret_cast<float2*>(g_xz + (size_t)r0 * 256 + col) =
                    make_float2(d[mi][n8][0], d[mi][n8][1]);
                *reinterpret_cast<float2*>(g_xz + (size_t)(r0 + 8) * 256 + col) =
                    make_float2(d[mi][n8][2], d[mi][n8][3]);
            }
        }
    } else {
        // Fused LSTM epilogue: dump z to smem (stride 258), then pointwise.
        float* zsm = reinterpret_cast<float*>(dsm);
#pragma unroll
        for (int mi = 0; mi < 4; mi++) {
            int r0 = wm + mi * 16 + (L >> 2);
#pragma unroll
            for (int n8 = 0; n8 < 8; n8++) {
                int col = wn + n8 * 8 + ((L & 3) << 1);
                *reinterpret_cast<float2*>(zsm + r0 * 258 + col) =
                    make_float2(d[mi][n8][0], d[mi][n8][1]);
                *reinterpret_cast<float2*>(zsm + (r0 + 8) * 258 + col) =
                    make_float2(d[mi][n8][2], d[mi][n8][3]);
            }
        }
        __syncthreads();
#pragma unroll 1
        for (int ii = 0; ii < 32; ii++) {
            int idx = tid + ii * 256;                 // 8192 (px, f) pairs
            int f  = idx & 63;
            int px = idx >> 6;
            int row = tile * 128 + px;
            int b_  = row >> 12, pix = row & 4095;
            size_t xzb = (((size_t)b_ * 16 + t) * 4096 + pix) * 256 + f;
            float zi = zsm[px * 258 + f      ] + g_xz[xzb      ] + bias[f];
            float zf = zsm[px * 258 + f +  64] + g_xz[xzb +  64] + bias[64 + f];
            float zg = zsm[px * 258 + f + 128] + g_xz[xzb + 128] + bias[128 + f];
            float zo = zsm[px * 258 + f + 192] + g_xz[xzb + 192] + bias[192 + f];
            float ig = __saturatef(0.2f * zi + 0.5f);
            float fg = __saturatef(0.2f * zf + 0.5f);
            float og = __saturatef(0.2f * zo + 0.5f);
            size_t ci = (size_t)row * 64 + f;
            float cn = fg * g_c[ci] + ig * tanhf(zg);
            float hn = og * tanhf(cn);
            g_c[ci]  = cn;
            g_hf[ci] = __float2half_rn(hn);
            float sc = gamma[f] * rsqrtf(var[f] + 1e-3f);
            out[(((size_t)b_ * 16 + t) * 4096 + pix) * 64 + f] =
                (hn - mean[f]) * sc + beta[f];
        }
    }
}

extern "C" void kernel_launch(void* const* d_in, const int* in_sizes, int n_in,
                              void* d_out, int out_size)
{
    const float* x     = (const float*)d_in[0];
    const float* W     = (const float*)d_in[1];
    const float* U     = (const float*)d_in[2];
    const float* b     = (const float*)d_in[3];
    const float* gamma = (const float*)d_in[4];
    const float* beta  = (const float*)d_in[5];
    const float* mean  = (const float*)d_in[6];
    const float* var   = (const float*)d_in[7];
    float* out = (float*)d_out;

    const int SMEM = 2 * 16384 + 2 * 65536;   // 163840 B

    cudaFuncSetAttribute((const void*)gemm_conv<0>,
                         cudaFuncAttributeMaxDynamicSharedMemorySize, SMEM);
    cudaFuncSetAttribute((const void*)gemm_conv<1>,
                         cudaFuncAttributeMaxDynamicSharedMemorySize, SMEM);

    prep_weights<<<896, 256>>>(W, U);
    x_convert<<<131072, 256>>>(x);
    zero_state<<<4096, 256>>>();

    // Input conv: 2048 tiles of 128 rows
    gemm_conv<0><<<2048, 256, SMEM>>>(nullptr, nullptr, nullptr, nullptr,
                                      nullptr, nullptr, 0);

    for (int t = 0; t < 16; t++)
        gemm_conv<1><<<128, 256, SMEM>>>(out, b, gamma, beta, mean, var, t);
}

// round 8
// speedup vs baseline: 4.2913x; 1.3201x over previous
#include <cuda_runtime.h>
#include <cuda_fp16.h>
#include <stdint.h>
#include <math.h>

// ---------------------------------------------------------------------------
// ConvLSTMBlock via ldmatrix + mma.sync (HMMA; harness PTX target is sm_103
// without 'a' so tcgen05 is unavailable).
//   input conv : GEMM M=262144, N=256, K=288(pad 320), A = im2col(x) stride2
//   recurrent  : GEMM M=16384,  N=256, K=576,          A = im2col(h) stride1
// Single-term fp16 (A and B rounded once); rel_err ~3.5e-4 < 1e-3.
// Recurrent kernel fuses the full LSTM pointwise + BN into its epilogue.
// R8 fix: recurrent kernel requests 132096B dynamic smem (fused epilogue's
// z-buffer = 128*258*4 B; R7 under-allocated 98304B -> smem OOB -> crash).
// ---------------------------------------------------------------------------

// ---- device scratch (allocation-free rule) ----
__device__ __align__(1024) float  g_xz[(size_t)64 * 4096 * 256];
__device__ __align__(1024) float  g_c [(size_t)4  * 4096 * 64];
__device__ __align__(1024) __half g_hf[(size_t)4  * 4096 * 64];
__device__ __align__(1024) __half g_xh[(size_t)64 * 128 * 128 * 32];
__device__ __align__(1024) __half g_UH[256 * 576];
__device__ __align__(1024) __half g_WH[256 * 320];

// ---- PTX helpers ----
__device__ __forceinline__ uint32_t s2u(const void* p) {
    uint32_t a;
    asm("{ .reg .u64 t; cvta.to.shared.u64 t, %1; cvt.u32.u64 %0, t; }"
        : "=r"(a) : "l"(p));
    return a;
}
__device__ __forceinline__ void cpa16(uint32_t dst, const void* src, uint32_t sz) {
    asm volatile("cp.async.cg.shared.global [%0], [%1], 16, %2;"
                 :: "r"(dst), "l"(src), "r"(sz));
}
__device__ __forceinline__ void cpcommit() {
    asm volatile("cp.async.commit_group;" ::: "memory");
}
template <int N> __device__ __forceinline__ void cpwait() {
    asm volatile("cp.async.wait_group %0;" :: "n"(N) : "memory");
}
__device__ __forceinline__ void ldm4(uint32_t* r, uint32_t addr) {
    asm volatile("ldmatrix.sync.aligned.m8n8.x4.shared.b16 {%0,%1,%2,%3}, [%4];"
                 : "=r"(r[0]), "=r"(r[1]), "=r"(r[2]), "=r"(r[3]) : "r"(addr));
}
__device__ __forceinline__ void mma16816(float* d, const uint32_t* a,
                                         uint32_t b0, uint32_t b1) {
    asm volatile(
        "mma.sync.aligned.m16n8k16.row.col.f32.f16.f16.f32 "
        "{%0,%1,%2,%3}, {%4,%5,%6,%7}, {%8,%9}, {%0,%1,%2,%3};"
        : "+f"(d[0]), "+f"(d[1]), "+f"(d[2]), "+f"(d[3])
        : "r"(a[0]), "r"(a[1]), "r"(a[2]), "r"(a[3]), "r"(b0), "r"(b1));
}

// ---- prep kernels ----
__global__ void prep_weights(const float* __restrict__ W, const float* __restrict__ U) {
    int idx = blockIdx.x * 256 + threadIdx.x;
    const int NU = 256 * 576;
    if (idx < NU) {
        int n = idx / 576, col = idx - n * 576;
        g_UH[idx] = __float2half_rn(U[(size_t)col * 256 + n]);
    } else {
        int j = idx - NU;
        if (j >= 256 * 320) return;
        int n = j / 320, col = j - n * 320;
        g_WH[j] = __float2half_rn((col < 288) ? W[(size_t)col * 256 + n] : 0.0f);
    }
}

__global__ void x_convert(const float* __restrict__ x) {
    size_t i = (size_t)blockIdx.x * 256 + threadIdx.x;
    if (i >= (size_t)64 * 128 * 128 * 32) return;
    g_xh[i] = __float2half_rn(x[i]);
}

__global__ void zero_state() {
    int i = blockIdx.x * 256 + threadIdx.x;   // 4096 blocks * 256
    g_c[i] = 0.0f;
    g_hf[i] = __half(0.0f);
}

// ---------------------------------------------------------------------------
// GEMM conv. CTA: 128 rows (pixels) x 256 cols (all 4F). 8 warps = 2M x 4N,
// warp tile 64x64. K-chunk 64 (4 k16 steps). Smem: A stage 16KB + B stage
// 32KB, double-buffered = 96KB GEMM footprint. XOR-16B swizzle.
// REC==1 fuses LSTM pointwise + BN epilogue (needs 132096B smem total).
// ---------------------------------------------------------------------------
template <int REC>
__global__ void __launch_bounds__(256, 1) gemm_conv(
    float* __restrict__ out, const float* __restrict__ bias,
    const float* __restrict__ gamma, const float* __restrict__ beta,
    const float* __restrict__ mean, const float* __restrict__ var, int t)
{
    constexpr int CIN    = REC ? 64 : 32;
    constexpr int CSH    = REC ? 6 : 5;
    constexpr int IN     = REC ? 64 : 128;
    constexpr int STRIDE = REC ? 1 : 2;
    constexpr int PADLO  = REC ? 1 : 0;
    constexpr int NCHUNK = REC ? 9 : 5;
    constexpr int KP     = REC ? 576 : 320;

    const __half* __restrict__ Asrc = REC ? g_hf : g_xh;
    const __half* __restrict__ Bh   = REC ? g_UH : g_WH;

    extern __shared__ char dsm[];
    const uint32_t smA = s2u(dsm);            // A stages: 2 x 16384
    const uint32_t smB = smA + 32768;         // B stages: 2 x 32768

    const int tid  = threadIdx.x;
    const int warp = tid >> 5;
    const int L    = tid & 31;
    const int tile = blockIdx.x;
    const int wm   = (warp >> 2) * 64;
    const int wn   = (warp & 3) * 64;

    // ldmatrix per-lane geometry
    const int sub  = L >> 3;
    const int ri16 = ((sub & 1) << 3) + (L & 7);
    const int us   = sub >> 1;

    int aRowB[4], aRM[4], bRowB[4], bRM[4];
#pragma unroll
    for (int mi = 0; mi < 4; mi++) {
        int r = wm + mi * 16 + ri16;
        aRowB[mi] = r * 128; aRM[mi] = r & 7;
    }
#pragma unroll
    for (int jj = 0; jj < 4; jj++) {
        int n = wn + jj * 16 + ri16;
        bRowB[jj] = n * 128; bRM[jj] = n & 7;
    }

    float d[4][8][4];
#pragma unroll
    for (int mi = 0; mi < 4; mi++)
#pragma unroll
        for (int n8 = 0; n8 < 8; n8++)
#pragma unroll
            for (int k = 0; k < 4; k++) d[mi][n8][k] = 0.0f;

    auto load_chunk = [&](int c, int s) {
        uint32_t sa = smA + (uint32_t)s * 16384u;
        uint32_t sb = smB + (uint32_t)s * 32768u;
#pragma unroll
        for (int j = 0; j < 4; j++) {               // A: 1024 16B units
            int i = tid + j * 256;
            int r = i >> 3, q = i & 7;
            int row = tile * 128 + r;
            int img = row >> 12, px = row & 4095, y = px >> 6, x = px & 63;
            int k = c * 64 + q * 8;
            int kpos = k >> CSH;
            int ci0 = k & (CIN - 1);
            int ky = (kpos >= 6) ? 2 : ((kpos >= 3) ? 1 : 0);
            int kx = kpos - 3 * ky;
            int sy = y * STRIDE + ky - PADLO;
            int sx = x * STRIDE + kx - PADLO;
            bool ok = (kpos < 9) && ((unsigned)sy < (unsigned)IN) &&
                      ((unsigned)sx < (unsigned)IN);
            size_t so = ok ? ((((size_t)img * IN + sy) * IN + sx) * CIN + ci0) : 0;
            uint32_t dst = sa + (uint32_t)(r * 128 + ((q ^ (r & 7)) << 4));
            cpa16(dst, Asrc + so, ok ? 16u : 0u);
        }
#pragma unroll
        for (int j = 0; j < 8; j++) {               // B: 2048 16B units
            int i = tid + j * 256;
            int n = i >> 3, q = i & 7;
            size_t so = (size_t)n * KP + c * 64 + q * 8;
            uint32_t dd = (uint32_t)(n * 128 + ((q ^ (n & 7)) << 4));
            cpa16(sb + dd, Bh + so, 16u);
        }
        cpcommit();
    };

    load_chunk(0, 0);

#pragma unroll 1
    for (int c = 0; c < NCHUNK; c++) {
        int s = c & 1;
        if (c + 1 < NCHUNK) { load_chunk(c + 1, s ^ 1); cpwait<1>(); }
        else                { cpwait<0>(); }
        __syncthreads();

        uint32_t sa = smA + (uint32_t)s * 16384u;
        uint32_t sb = smB + (uint32_t)s * 32768u;
#pragma unroll
        for (int kk = 0; kk < 4; kk++) {
            uint32_t a[4][4];
#pragma unroll
            for (int mi = 0; mi < 4; mi++)
                ldm4(a[mi], sa + aRowB[mi] + ((((kk << 1) | us) ^ aRM[mi]) << 4));
#pragma unroll
            for (int jj = 0; jj < 4; jj++) {
                uint32_t b[4];
                ldm4(b, sb + bRowB[jj] + ((((kk << 1) | us) ^ bRM[jj]) << 4));
#pragma unroll
                for (int mi = 0; mi < 4; mi++) {
                    mma16816(d[mi][2 * jj],     a[mi], b[0], b[2]);
                    mma16816(d[mi][2 * jj + 1], a[mi], b[1], b[3]);
                }
            }
        }
        __syncthreads();
    }

    if (!REC) {
        // Plain epilogue: store to g_xz fp32 [row][256]
#pragma unroll
        for (int mi = 0; mi < 4; mi++) {
            int r0 = tile * 128 + wm + mi * 16 + (L >> 2);
#pragma unroll
            for (int n8 = 0; n8 < 8; n8++) {
                int col = wn + n8 * 8 + ((L & 3) << 1);
                *reinterpret_cast<float2*>(g_xz + (size_t)r0 * 256 + col) =
                    make_float2(d[mi][n8][0], d[mi][n8][1]);
                *reinterpret_cast<float2*>(g_xz + (size_t)(r0 + 8) * 256 + col) =
                    make_float2(d[mi][n8][2], d[mi][n8][3]);
            }
        }
    } else {
        // Fused LSTM epilogue: dump z to smem (stride 258), then pointwise.
        // Requires 128*258*4 = 132096 B of dynamic smem (allocated for REC).
        float* zsm = reinterpret_cast<float*>(dsm);
#pragma unroll
        for (int mi = 0; mi < 4; mi++) {
            int r0 = wm + mi * 16 + (L >> 2);
#pragma unroll
            for (int n8 = 0; n8 < 8; n8++) {
                int col = wn + n8 * 8 + ((L & 3) << 1);
                *reinterpret_cast<float2*>(zsm + r0 * 258 + col) =
                    make_float2(d[mi][n8][0], d[mi][n8][1]);
                *reinterpret_cast<float2*>(zsm + (r0 + 8) * 258 + col) =
                    make_float2(d[mi][n8][2], d[mi][n8][3]);
            }
        }
        __syncthreads();
#pragma unroll 1
        for (int ii = 0; ii < 32; ii++) {
            int idx = tid + ii * 256;                 // 8192 (px, f) pairs
            int f  = idx & 63;
            int px = idx >> 6;
            int row = tile * 128 + px;
            int b_  = row >> 12, pix = row & 4095;
            size_t xzb = (((size_t)b_ * 16 + t) * 4096 + pix) * 256 + f;
            float zi = zsm[px * 258 + f      ] + g_xz[xzb      ] + bias[f];
            float zf = zsm[px * 258 + f +  64] + g_xz[xzb +  64] + bias[64 + f];
            float zg = zsm[px * 258 + f + 128] + g_xz[xzb + 128] + bias[128 + f];
            float zo = zsm[px * 258 + f + 192] + g_xz[xzb + 192] + bias[192 + f];
            float ig = __saturatef(0.2f * zi + 0.5f);
            float fg = __saturatef(0.2f * zf + 0.5f);
            float og = __saturatef(0.2f * zo + 0.5f);
            size_t ci = (size_t)row * 64 + f;
            float cn = fg * g_c[ci] + ig * tanhf(zg);
            float hn = og * tanhf(cn);
            g_c[ci]  = cn;
            g_hf[ci] = __float2half_rn(hn);
            float sc = gamma[f] * rsqrtf(var[f] + 1e-3f);
            out[(((size_t)b_ * 16 + t) * 4096 + pix) * 64 + f] =
                (hn - mean[f]) * sc + beta[f];
        }
    }
}

extern "C" void kernel_launch(void* const* d_in, const int* in_sizes, int n_in,
                              void* d_out, int out_size)
{
    const float* x     = (const float*)d_in[0];
    const float* W     = (const float*)d_in[1];
    const float* U     = (const float*)d_in[2];
    const float* b     = (const float*)d_in[3];
    const float* gamma = (const float*)d_in[4];
    const float* beta  = (const float*)d_in[5];
    const float* mean  = (const float*)d_in[6];
    const float* var   = (const float*)d_in[7];
    float* out = (float*)d_out;

    const int SMEM_IN  = 2 * 16384 + 2 * 32768;   // 98304 B (GEMM only)
    const int SMEM_REC = 128 * 258 * 4;           // 132096 B (fused epilogue)

    cudaFuncSetAttribute((const void*)gemm_conv<0>,
                         cudaFuncAttributeMaxDynamicSharedMemorySize, SMEM_IN);
    cudaFuncSetAttribute((const void*)gemm_conv<1>,
                         cudaFuncAttributeMaxDynamicSharedMemorySize, SMEM_REC);

    prep_weights<<<896, 256>>>(W, U);
    x_convert<<<131072, 256>>>(x);
    zero_state<<<4096, 256>>>();

    // Input conv: 2048 tiles of 128 rows
    gemm_conv<0><<<2048, 256, SMEM_IN>>>(nullptr, nullptr, nullptr, nullptr,
                                         nullptr, nullptr, 0);

    for (int t = 0; t < 16; t++)
        gemm_conv<1><<<128, 256, SMEM_REC>>>(out, b, gamma, beta, mean, var, t);
}

// round 9
// speedup vs baseline: 4.9858x; 1.1618x over previous
#include <cuda_runtime.h>
#include <cuda_fp16.h>
#include <stdint.h>
#include <math.h>

// ---------------------------------------------------------------------------
// ConvLSTMBlock via ldmatrix + mma.sync (HMMA; harness PTX target is sm_103
// without 'a' so tcgen05 is unavailable).
//   input conv : GEMM M=262144, N=256, K=288(pad 320), A = im2col(x) stride2
//   recurrent  : GEMM M=16384,  N=256, K=576,          A = im2col(h) stride1
// Single-term fp16; recurrent kernel fuses LSTM pointwise + BN epilogue.
// R9: 512 threads / 16 warps per CTA (warp tile 64x32) for latency hiding;
//     g_xz stored fp16 (halves input-epilogue writes + rec-epilogue reads).
// ---------------------------------------------------------------------------

// ---- device scratch (allocation-free rule) ----
__device__ __align__(1024) __half g_xzh[(size_t)64 * 4096 * 256];
__device__ __align__(1024) float  g_c [(size_t)4  * 4096 * 64];
__device__ __align__(1024) __half g_hf[(size_t)4  * 4096 * 64];
__device__ __align__(1024) __half g_xh[(size_t)64 * 128 * 128 * 32];
__device__ __align__(1024) __half g_UH[256 * 576];
__device__ __align__(1024) __half g_WH[256 * 320];

// ---- PTX helpers ----
__device__ __forceinline__ uint32_t s2u(const void* p) {
    uint32_t a;
    asm("{ .reg .u64 t; cvta.to.shared.u64 t, %1; cvt.u32.u64 %0, t; }"
        : "=r"(a) : "l"(p));
    return a;
}
__device__ __forceinline__ void cpa16(uint32_t dst, const void* src, uint32_t sz) {
    asm volatile("cp.async.cg.shared.global [%0], [%1], 16, %2;"
                 :: "r"(dst), "l"(src), "r"(sz));
}
__device__ __forceinline__ void cpcommit() {
    asm volatile("cp.async.commit_group;" ::: "memory");
}
template <int N> __device__ __forceinline__ void cpwait() {
    asm volatile("cp.async.wait_group %0;" :: "n"(N) : "memory");
}
__device__ __forceinline__ void ldm4(uint32_t* r, uint32_t addr) {
    asm volatile("ldmatrix.sync.aligned.m8n8.x4.shared.b16 {%0,%1,%2,%3}, [%4];"
                 : "=r"(r[0]), "=r"(r[1]), "=r"(r[2]), "=r"(r[3]) : "r"(addr));
}
__device__ __forceinline__ void mma16816(float* d, const uint32_t* a,
                                         uint32_t b0, uint32_t b1) {
    asm volatile(
        "mma.sync.aligned.m16n8k16.row.col.f32.f16.f16.f32 "
        "{%0,%1,%2,%3}, {%4,%5,%6,%7}, {%8,%9}, {%0,%1,%2,%3};"
        : "+f"(d[0]), "+f"(d[1]), "+f"(d[2]), "+f"(d[3])
        : "r"(a[0]), "r"(a[1]), "r"(a[2]), "r"(a[3]), "r"(b0), "r"(b1));
}

// ---- prep kernels ----
__global__ void prep_weights(const float* __restrict__ W, const float* __restrict__ U) {
    int idx = blockIdx.x * 256 + threadIdx.x;
    const int NU = 256 * 576;
    if (idx < NU) {
        int n = idx / 576, col = idx - n * 576;
        g_UH[idx] = __float2half_rn(U[(size_t)col * 256 + n]);
    } else {
        int j = idx - NU;
        if (j >= 256 * 320) return;
        int n = j / 320, col = j - n * 320;
        g_WH[j] = __float2half_rn((col < 288) ? W[(size_t)col * 256 + n] : 0.0f);
    }
}

__global__ void x_convert(const float* __restrict__ x) {
    size_t i = (size_t)blockIdx.x * 256 + threadIdx.x;
    if (i >= (size_t)64 * 128 * 128 * 32) return;
    g_xh[i] = __float2half_rn(x[i]);
}

__global__ void zero_state() {
    int i = blockIdx.x * 256 + threadIdx.x;   // 4096 blocks * 256
    g_c[i] = 0.0f;
    g_hf[i] = __half(0.0f);
}

// ---------------------------------------------------------------------------
// GEMM conv. CTA: 128 rows (pixels) x 256 cols. 16 warps = 2M x 8N, warp
// tile 64x32. K-chunk 64 (4 k16 steps). Smem: A stage 16KB + B stage 32KB,
// double-buffered = 96KB GEMM footprint. XOR-16B swizzle.
// REC==1 fuses LSTM pointwise + BN epilogue (132096B smem).
// ---------------------------------------------------------------------------
template <int REC>
__global__ void __launch_bounds__(512, 1) gemm_conv(
    float* __restrict__ out, const float* __restrict__ bias,
    const float* __restrict__ gamma, const float* __restrict__ beta,
    const float* __restrict__ mean, const float* __restrict__ var, int t)
{
    constexpr int CIN    = REC ? 64 : 32;
    constexpr int CSH    = REC ? 6 : 5;
    constexpr int IN     = REC ? 64 : 128;
    constexpr int STRIDE = REC ? 1 : 2;
    constexpr int PADLO  = REC ? 1 : 0;
    constexpr int NCHUNK = REC ? 9 : 5;
    constexpr int KP     = REC ? 576 : 320;

    const __half* __restrict__ Asrc = REC ? g_hf : g_xh;
    const __half* __restrict__ Bsrc = REC ? g_UH : g_WH;

    extern __shared__ char dsm[];
    const uint32_t smA = s2u(dsm);            // A stages: 2 x 16384
    const uint32_t smB = smA + 32768;         // B stages: 2 x 32768

    const int tid  = threadIdx.x;
    const int warp = tid >> 5;
    const int L    = tid & 31;
    const int tile = blockIdx.x;
    const int wm   = (warp >> 3) * 64;        // 2 M-groups
    const int wn   = (warp & 7) * 32;         // 8 N-groups

    // ldmatrix per-lane geometry
    const int sub  = L >> 3;
    const int ri16 = ((sub & 1) << 3) + (L & 7);
    const int us   = sub >> 1;

    int aRowB[4], aRM[4], bRowB[2], bRM[2];
#pragma unroll
    for (int mi = 0; mi < 4; mi++) {
        int r = wm + mi * 16 + ri16;
        aRowB[mi] = r * 128; aRM[mi] = r & 7;
    }
#pragma unroll
    for (int jj = 0; jj < 2; jj++) {
        int n = wn + jj * 16 + ri16;
        bRowB[jj] = n * 128; bRM[jj] = n & 7;
    }

    float d[4][4][4];                          // [mi][n8][frag]
#pragma unroll
    for (int mi = 0; mi < 4; mi++)
#pragma unroll
        for (int n8 = 0; n8 < 4; n8++)
#pragma unroll
            for (int k = 0; k < 4; k++) d[mi][n8][k] = 0.0f;

    auto load_chunk = [&](int c, int s) {
        uint32_t sa = smA + (uint32_t)s * 16384u;
        uint32_t sb = smB + (uint32_t)s * 32768u;
#pragma unroll
        for (int j = 0; j < 2; j++) {               // A: 1024 16B units
            int i = tid + j * 512;
            int r = i >> 3, q = i & 7;
            int row = tile * 128 + r;
            int img = row >> 12, px = row & 4095, y = px >> 6, x = px & 63;
            int k = c * 64 + q * 8;
            int kpos = k >> CSH;
            int ci0 = k & (CIN - 1);
            int ky = (kpos >= 6) ? 2 : ((kpos >= 3) ? 1 : 0);
            int kx = kpos - 3 * ky;
            int sy = y * STRIDE + ky - PADLO;
            int sx = x * STRIDE + kx - PADLO;
            bool ok = (kpos < 9) && ((unsigned)sy < (unsigned)IN) &&
                      ((unsigned)sx < (unsigned)IN);
            size_t so = ok ? ((((size_t)img * IN + sy) * IN + sx) * CIN + ci0) : 0;
            uint32_t dst = sa + (uint32_t)(r * 128 + ((q ^ (r & 7)) << 4));
            cpa16(dst, Asrc + so, ok ? 16u : 0u);
        }
#pragma unroll
        for (int j = 0; j < 4; j++) {               // B: 2048 16B units
            int i = tid + j * 512;
            int n = i >> 3, q = i & 7;
            size_t so = (size_t)n * KP + c * 64 + q * 8;
            uint32_t dd = (uint32_t)(n * 128 + ((q ^ (n & 7)) << 4));
            cpa16(sb + dd, Bsrc + so, 16u);
        }
        cpcommit();
    };

    load_chunk(0, 0);

#pragma unroll 1
    for (int c = 0; c < NCHUNK; c++) {
        int s = c & 1;
        if (c + 1 < NCHUNK) { load_chunk(c + 1, s ^ 1); cpwait<1>(); }
        else                { cpwait<0>(); }
        __syncthreads();

        uint32_t sa = smA + (uint32_t)s * 16384u;
        uint32_t sb = smB + (uint32_t)s * 32768u;
#pragma unroll
        for (int kk = 0; kk < 4; kk++) {
            uint32_t a[4][4];
#pragma unroll
            for (int mi = 0; mi < 4; mi++)
                ldm4(a[mi], sa + aRowB[mi] + ((((kk << 1) | us) ^ aRM[mi]) << 4));
#pragma unroll
            for (int jj = 0; jj < 2; jj++) {
                uint32_t b[4];
                ldm4(b, sb + bRowB[jj] + ((((kk << 1) | us) ^ bRM[jj]) << 4));
#pragma unroll
                for (int mi = 0; mi < 4; mi++) {
                    mma16816(d[mi][2 * jj],     a[mi], b[0], b[2]);
                    mma16816(d[mi][2 * jj + 1], a[mi], b[1], b[3]);
                }
            }
        }
        __syncthreads();
    }

    if (!REC) {
        // Epilogue: store fp16 to g_xzh [row][256]
#pragma unroll
        for (int mi = 0; mi < 4; mi++) {
            int r0 = tile * 128 + wm + mi * 16 + (L >> 2);
#pragma unroll
            for (int n8 = 0; n8 < 4; n8++) {
                int col = wn + n8 * 8 + ((L & 3) << 1);
                *reinterpret_cast<__half2*>(g_xzh + (size_t)r0 * 256 + col) =
                    __floats2half2_rn(d[mi][n8][0], d[mi][n8][1]);
                *reinterpret_cast<__half2*>(g_xzh + (size_t)(r0 + 8) * 256 + col) =
                    __floats2half2_rn(d[mi][n8][2], d[mi][n8][3]);
            }
        }
    } else {
        // Fused LSTM epilogue: dump z to smem (stride 258), then pointwise.
        // Requires 128*258*4 = 132096 B of dynamic smem.
        float* zsm = reinterpret_cast<float*>(dsm);
#pragma unroll
        for (int mi = 0; mi < 4; mi++) {
            int r0 = wm + mi * 16 + (L >> 2);
#pragma unroll
            for (int n8 = 0; n8 < 4; n8++) {
                int col = wn + n8 * 8 + ((L & 3) << 1);
                *reinterpret_cast<float2*>(zsm + r0 * 258 + col) =
                    make_float2(d[mi][n8][0], d[mi][n8][1]);
                *reinterpret_cast<float2*>(zsm + (r0 + 8) * 258 + col) =
                    make_float2(d[mi][n8][2], d[mi][n8][3]);
            }
        }
        __syncthreads();
#pragma unroll 1
        for (int ii = 0; ii < 16; ii++) {
            int idx = tid + ii * 512;                 // 8192 (px, f) pairs
            int f  = idx & 63;
            int px = idx >> 6;
            int row = tile * 128 + px;
            int b_  = row >> 12, pix = row & 4095;
            size_t xzb = (((size_t)b_ * 16 + t) * 4096 + pix) * 256 + f;
            float zi = zsm[px * 258 + f      ] + __half2float(g_xzh[xzb      ]) + bias[f];
            float zf = zsm[px * 258 + f +  64] + __half2float(g_xzh[xzb +  64]) + bias[64 + f];
            float zg = zsm[px * 258 + f + 128] + __half2float(g_xzh[xzb + 128]) + bias[128 + f];
            float zo = zsm[px * 258 + f + 192] + __half2float(g_xzh[xzb + 192]) + bias[192 + f];
            float ig = __saturatef(0.2f * zi + 0.5f);
            float fg = __saturatef(0.2f * zf + 0.5f);
            float og = __saturatef(0.2f * zo + 0.5f);
            size_t ci = (size_t)row * 64 + f;
            float cn = fg * g_c[ci] + ig * tanhf(zg);
            float hn = og * tanhf(cn);
            g_c[ci]  = cn;
            g_hf[ci] = __float2half_rn(hn);
            float sc = gamma[f] * rsqrtf(var[f] + 1e-3f);
            out[(((size_t)b_ * 16 + t) * 4096 + pix) * 64 + f] =
                (hn - mean[f]) * sc + beta[f];
        }
    }
}

extern "C" void kernel_launch(void* const* d_in, const int* in_sizes, int n_in,
                              void* d_out, int out_size)
{
    const float* x     = (const float*)d_in[0];
    const float* W     = (const float*)d_in[1];
    const float* U     = (const float*)d_in[2];
    const float* b     = (const float*)d_in[3];
    const float* gamma = (const float*)d_in[4];
    const float* beta  = (const float*)d_in[5];
    const float* mean  = (const float*)d_in[6];
    const float* var   = (const float*)d_in[7];
    float* out = (float*)d_out;

    const int SMEM_IN  = 2 * 16384 + 2 * 32768;   // 98304 B (GEMM only)
    const int SMEM_REC = 128 * 258 * 4;           // 132096 B (fused epilogue)

    cudaFuncSetAttribute((const void*)gemm_conv<0>,
                         cudaFuncAttributeMaxDynamicSharedMemorySize, SMEM_IN);
    cudaFuncSetAttribute((const void*)gemm_conv<1>,
                         cudaFuncAttributeMaxDynamicSharedMemorySize, SMEM_REC);

    prep_weights<<<896, 256>>>(W, U);
    x_convert<<<131072, 256>>>(x);
    zero_state<<<4096, 256>>>();

    // Input conv: 2048 tiles of 128 rows
    gemm_conv<0><<<2048, 512, SMEM_IN>>>(nullptr, nullptr, nullptr, nullptr,
                                         nullptr, nullptr, 0);

    for (int t = 0; t < 16; t++)
        gemm_conv<1><<<128, 512, SMEM_REC>>>(out, b, gamma, beta, mean, var, t);
}

// round 10
// speedup vs baseline: 5.6943x; 1.1421x over previous
#include <cuda_runtime.h>
#include <cuda_fp16.h>
#include <stdint.h>
#include <math.h>

// ---------------------------------------------------------------------------
// ConvLSTMBlock via ldmatrix + mma.sync (HMMA; harness PTX target is sm_103
// without 'a' so tcgen05 is unavailable).
//   input conv : GEMM M=262144, N=256, K=288(pad 320), A = im2col(x) stride2
//   recurrent  : GEMM M=16384,  N=256, K=576,          A = im2col(h) stride1
// Single-term fp16; recurrent kernel fuses LSTM pointwise + BN epilogue.
// R10: hoisted im2col address math out of the chunk loop (issue-bound fix),
//      t=0 step skips the GEMM (h0=0), zero_state removed, x_convert
//      vectorized 8-wide.
// ---------------------------------------------------------------------------

// ---- device scratch (allocation-free rule) ----
__device__ __align__(1024) __half g_xzh[(size_t)64 * 4096 * 256];
__device__ __align__(1024) float  g_c [(size_t)4  * 4096 * 64];
__device__ __align__(1024) __half g_hf[(size_t)4  * 4096 * 64];
__device__ __align__(1024) __half g_xh[(size_t)64 * 128 * 128 * 32];
__device__ __align__(1024) __half g_UH[256 * 576];
__device__ __align__(1024) __half g_WH[256 * 320];

// ---- PTX helpers ----
__device__ __forceinline__ uint32_t s2u(const void* p) {
    uint32_t a;
    asm("{ .reg .u64 t; cvta.to.shared.u64 t, %1; cvt.u32.u64 %0, t; }"
        : "=r"(a) : "l"(p));
    return a;
}
__device__ __forceinline__ void cpa16(uint32_t dst, const void* src, uint32_t sz) {
    asm volatile("cp.async.cg.shared.global [%0], [%1], 16, %2;"
                 :: "r"(dst), "l"(src), "r"(sz));
}
__device__ __forceinline__ void cpcommit() {
    asm volatile("cp.async.commit_group;" ::: "memory");
}
template <int N> __device__ __forceinline__ void cpwait() {
    asm volatile("cp.async.wait_group %0;" :: "n"(N) : "memory");
}
__device__ __forceinline__ void ldm4(uint32_t* r, uint32_t addr) {
    asm volatile("ldmatrix.sync.aligned.m8n8.x4.shared.b16 {%0,%1,%2,%3}, [%4];"
                 : "=r"(r[0]), "=r"(r[1]), "=r"(r[2]), "=r"(r[3]) : "r"(addr));
}
__device__ __forceinline__ void mma16816(float* d, const uint32_t* a,
                                         uint32_t b0, uint32_t b1) {
    asm volatile(
        "mma.sync.aligned.m16n8k16.row.col.f32.f16.f16.f32 "
        "{%0,%1,%2,%3}, {%4,%5,%6,%7}, {%8,%9}, {%0,%1,%2,%3};"
        : "+f"(d[0]), "+f"(d[1]), "+f"(d[2]), "+f"(d[3])
        : "r"(a[0]), "r"(a[1]), "r"(a[2]), "r"(a[3]), "r"(b0), "r"(b1));
}

// ---- prep kernels ----
__global__ void prep_weights(const float* __restrict__ W, const float* __restrict__ U) {
    int idx = blockIdx.x * 256 + threadIdx.x;
    const int NU = 256 * 576;
    if (idx < NU) {
        int n = idx / 576, col = idx - n * 576;
        g_UH[idx] = __float2half_rn(U[(size_t)col * 256 + n]);
    } else {
        int j = idx - NU;
        if (j >= 256 * 320) return;
        int n = j / 320, col = j - n * 320;
        g_WH[j] = __float2half_rn((col < 288) ? W[(size_t)col * 256 + n] : 0.0f);
    }
}

__global__ void x_convert(const float4* __restrict__ x) {
    size_t i = (size_t)blockIdx.x * 256 + threadIdx.x;   // 8 floats per thread
    if (i >= (size_t)64 * 128 * 128 * 32 / 8) return;
    float4 v0 = x[2 * i], v1 = x[2 * i + 1];
    __half2 h0 = __floats2half2_rn(v0.x, v0.y);
    __half2 h1 = __floats2half2_rn(v0.z, v0.w);
    __half2 h2 = __floats2half2_rn(v1.x, v1.y);
    __half2 h3 = __floats2half2_rn(v1.z, v1.w);
    uint4 u;
    u.x = *reinterpret_cast<uint32_t*>(&h0);
    u.y = *reinterpret_cast<uint32_t*>(&h1);
    u.z = *reinterpret_cast<uint32_t*>(&h2);
    u.w = *reinterpret_cast<uint32_t*>(&h3);
    reinterpret_cast<uint4*>(g_xh)[i] = u;
}

// ---- t=0 pointwise: h0=c0=0 so z = xz + b; no recurrent GEMM needed ----
__global__ void t0_pointwise(
    float* __restrict__ out, const float* __restrict__ bias,
    const float* __restrict__ gamma, const float* __restrict__ beta,
    const float* __restrict__ mean, const float* __restrict__ var)
{
    int idx = blockIdx.x * 512 + threadIdx.x;   // 1,048,576 threads
    int f  = idx & 63;
    int bp = idx >> 6;
    int b_ = idx >> 18;
    int pix = bp & 4095;
    size_t xzb = (((size_t)b_ * 16) * 4096 + pix) * 256 + f;
    float zi = __half2float(g_xzh[xzb      ]) + bias[f];
    float zg = __half2float(g_xzh[xzb + 128]) + bias[128 + f];
    float zo = __half2float(g_xzh[xzb + 192]) + bias[192 + f];
    float ig = __saturatef(0.2f * zi + 0.5f);
    float og = __saturatef(0.2f * zo + 0.5f);
    float cn = ig * tanhf(zg);
    float hn = og * tanhf(cn);
    g_c[idx]  = cn;
    g_hf[idx] = __float2half_rn(hn);
    float sc = gamma[f] * rsqrtf(var[f] + 1e-3f);
    out[(((size_t)b_ * 16) * 4096 + pix) * 64 + f] = (hn - mean[f]) * sc + beta[f];
}

// ---------------------------------------------------------------------------
// GEMM conv. CTA: 128 rows (pixels) x 256 cols. 16 warps = 2M x 8N, warp
// tile 64x32. K-chunk 64 (4 k16 steps). Smem: A stage 16KB + B stage 32KB,
// double-buffered. All gather address math hoisted; per-chunk is shifts/adds.
// REC==1 fuses LSTM pointwise + BN epilogue (132096B smem).
// ---------------------------------------------------------------------------
template <int REC>
__global__ void __launch_bounds__(512, 1) gemm_conv(
    float* __restrict__ out, const float* __restrict__ bias,
    const float* __restrict__ gamma, const float* __restrict__ beta,
    const float* __restrict__ mean, const float* __restrict__ var, int t)
{
    constexpr int CIN    = REC ? 64 : 32;
    constexpr int LOGCIN = REC ? 6 : 5;
    constexpr int IN     = REC ? 64 : 128;
    constexpr int LOGIN  = REC ? 6 : 7;
    constexpr int STRIDE = REC ? 1 : 2;
    constexpr int PADLO  = REC ? 1 : 0;
    constexpr int NCHUNK = REC ? 9 : 5;
    constexpr int KP     = REC ? 576 : 320;

    const __half* __restrict__ Asrc = REC ? g_hf : g_xh;
    const __half* __restrict__ Bsrc = REC ? g_UH : g_WH;

    extern __shared__ char dsm[];
    const uint32_t smA = s2u(dsm);            // A stages: 2 x 16384
    const uint32_t smB = smA + 32768;         // B stages: 2 x 32768

    const int tid  = threadIdx.x;
    const int warp = tid >> 5;
    const int L    = tid & 31;
    const int tile = blockIdx.x;
    const int wm   = (warp >> 3) * 64;        // 2 M-groups
    const int wn   = (warp & 7) * 32;         // 8 N-groups

    // ---- hoisted per-thread load geometry ----
    const __half* aBase[2];
    uint32_t aDst[2];
    int aY[2], aX[2], aQh[2];
#pragma unroll
    for (int j = 0; j < 2; j++) {
        int i = tid + j * 512;
        int r = i >> 3, q = i & 7;
        int row = tile * 128 + r;
        int img = row >> 12, px = row & 4095;
        aY[j] = px >> 6;
        aX[j] = px & 63;
        aQh[j] = q >> 2;                       // kpos sub-select (input conv)
        int ci0 = REC ? (q << 3) : ((q & 3) << 3);
        aBase[j] = Asrc + ((size_t)img << (2 * LOGIN + LOGCIN)) + ci0;
        aDst[j] = (uint32_t)(r * 128 + ((q ^ (r & 7)) << 4));
    }
    const __half* bBase[4];
    uint32_t bDst[4];
#pragma unroll
    for (int j = 0; j < 4; j++) {
        int i = tid + j * 512;
        int n = i >> 3, q = i & 7;
        bBase[j] = Bsrc + n * KP + q * 8;
        bDst[j] = (uint32_t)(n * 128 + ((q ^ (n & 7)) << 4));
    }

    // ldmatrix per-lane geometry
    const int sub  = L >> 3;
    const int ri16 = ((sub & 1) << 3) + (L & 7);
    const int us   = sub >> 1;

    int aRowB[4], aRM[4], bRowB[2], bRM[2];
#pragma unroll
    for (int mi = 0; mi < 4; mi++) {
        int r = wm + mi * 16 + ri16;
        aRowB[mi] = r * 128; aRM[mi] = r & 7;
    }
#pragma unroll
    for (int jj = 0; jj < 2; jj++) {
        int n = wn + jj * 16 + ri16;
        bRowB[jj] = n * 128; bRM[jj] = n & 7;
    }

    float d[4][4][4];
#pragma unroll
    for (int mi = 0; mi < 4; mi++)
#pragma unroll
        for (int n8 = 0; n8 < 4; n8++)
#pragma unroll
            for (int k = 0; k < 4; k++) d[mi][n8][k] = 0.0f;

    auto load_chunk = [&](int c, int s) {
        uint32_t sa = smA + (uint32_t)s * 16384u;
        uint32_t sb = smB + (uint32_t)s * 32768u;
#pragma unroll
        for (int j = 0; j < 2; j++) {
            int kpos = REC ? c : (2 * c + aQh[j]);
            int ky = (kpos >= 6) ? 2 : ((kpos >= 3) ? 1 : 0);
            int kx = kpos - 3 * ky;
            int sy = aY[j] * STRIDE + ky - PADLO;
            int sx = aX[j] * STRIDE + kx - PADLO;
            bool ok = (kpos < 9) && ((unsigned)sy < (unsigned)IN) &&
                      ((unsigned)sx < (unsigned)IN);
            uint32_t off = ok ? (uint32_t)((((sy << LOGIN) + sx) << LOGCIN)) : 0u;
            cpa16(sa + aDst[j], aBase[j] + off, ok ? 16u : 0u);
        }
#pragma unroll
        for (int j = 0; j < 4; j++)
            cpa16(sb + bDst[j], bBase[j] + (c << 6), 16u);
        cpcommit();
    };

    load_chunk(0, 0);

#pragma unroll 1
    for (int c = 0; c < NCHUNK; c++) {
        int s = c & 1;
        if (c + 1 < NCHUNK) { load_chunk(c + 1, s ^ 1); cpwait<1>(); }
        else                { cpwait<0>(); }
        __syncthreads();

        uint32_t sa = smA + (uint32_t)s * 16384u;
        uint32_t sb = smB + (uint32_t)s * 32768u;
#pragma unroll
        for (int kk = 0; kk < 4; kk++) {
            uint32_t a[4][4];
#pragma unroll
            for (int mi = 0; mi < 4; mi++)
                ldm4(a[mi], sa + aRowB[mi] + ((((kk << 1) | us) ^ aRM[mi]) << 4));
#pragma unroll
            for (int jj = 0; jj < 2; jj++) {
                uint32_t b[4];
                ldm4(b, sb + bRowB[jj] + ((((kk << 1) | us) ^ bRM[jj]) << 4));
#pragma unroll
                for (int mi = 0; mi < 4; mi++) {
                    mma16816(d[mi][2 * jj],     a[mi], b[0], b[2]);
                    mma16816(d[mi][2 * jj + 1], a[mi], b[1], b[3]);
                }
            }
        }
        __syncthreads();
    }

    if (!REC) {
        // Epilogue: store fp16 to g_xzh [row][256]
#pragma unroll
        for (int mi = 0; mi < 4; mi++) {
            int r0 = tile * 128 + wm + mi * 16 + (L >> 2);
#pragma unroll
            for (int n8 = 0; n8 < 4; n8++) {
                int col = wn + n8 * 8 + ((L & 3) << 1);
                *reinterpret_cast<__half2*>(g_xzh + (size_t)r0 * 256 + col) =
                    __floats2half2_rn(d[mi][n8][0], d[mi][n8][1]);
                *reinterpret_cast<__half2*>(g_xzh + (size_t)(r0 + 8) * 256 + col) =
                    __floats2half2_rn(d[mi][n8][2], d[mi][n8][3]);
            }
        }
    } else {
        // Fused LSTM epilogue: dump z to smem (stride 258), then pointwise.
        float* zsm = reinterpret_cast<float*>(dsm);
#pragma unroll
        for (int mi = 0; mi < 4; mi++) {
            int r0 = wm + mi * 16 + (L >> 2);
#pragma unroll
            for (int n8 = 0; n8 < 4; n8++) {
                int col = wn + n8 * 8 + ((L & 3) << 1);
                *reinterpret_cast<float2*>(zsm + r0 * 258 + col) =
                    make_float2(d[mi][n8][0], d[mi][n8][1]);
                *reinterpret_cast<float2*>(zsm + (r0 + 8) * 258 + col) =
                    make_float2(d[mi][n8][2], d[mi][n8][3]);
            }
        }
        __syncthreads();
#pragma unroll 1
        for (int ii = 0; ii < 16; ii++) {
            int idx = tid + ii * 512;                 // 8192 (px, f) pairs
            int f  = idx & 63;
            int px = idx >> 6;
            int row = tile * 128 + px;
            int b_  = row >> 12, pix = row & 4095;
            size_t xzb = (((size_t)b_ * 16 + t) * 4096 + pix) * 256 + f;
            float zi = zsm[px * 258 + f      ] + __half2float(g_xzh[xzb      ]) + bias[f];
            float zf = zsm[px * 258 + f +  64] + __half2float(g_xzh[xzb +  64]) + bias[64 + f];
            float zg = zsm[px * 258 + f + 128] + __half2float(g_xzh[xzb + 128]) + bias[128 + f];
            float zo = zsm[px * 258 + f + 192] + __half2float(g_xzh[xzb + 192]) + bias[192 + f];
            float ig = __saturatef(0.2f * zi + 0.5f);
            float fg = __saturatef(0.2f * zf + 0.5f);
            float og = __saturatef(0.2f * zo + 0.5f);
            size_t ci = (size_t)row * 64 + f;
            float cn = fg * g_c[ci] + ig * tanhf(zg);
            float hn = og * tanhf(cn);
            g_c[ci]  = cn;
            g_hf[ci] = __float2half_rn(hn);
            float sc = gamma[f] * rsqrtf(var[f] + 1e-3f);
            out[(((size_t)b_ * 16 + t) * 4096 + pix) * 64 + f] =
                (hn - mean[f]) * sc + beta[f];
        }
    }
}

extern "C" void kernel_launch(void* const* d_in, const int* in_sizes, int n_in,
                              void* d_out, int out_size)
{
    const float* x     = (const float*)d_in[0];
    const float* W     = (const float*)d_in[1];
    const float* U     = (const float*)d_in[2];
    const float* b     = (const float*)d_in[3];
    const float* gamma = (const float*)d_in[4];
    const float* beta  = (const float*)d_in[5];
    const float* mean  = (const float*)d_in[6];
    const float* var   = (const float*)d_in[7];
    float* out = (float*)d_out;

    const int SMEM_IN  = 2 * 16384 + 2 * 32768;   // 98304 B (GEMM only)
    const int SMEM_REC = 128 * 258 * 4;           // 132096 B (fused epilogue)

    cudaFuncSetAttribute((const void*)gemm_conv<0>,
                         cudaFuncAttributeMaxDynamicSharedMemorySize, SMEM_IN);
    cudaFuncSetAttribute((const void*)gemm_conv<1>,
                         cudaFuncAttributeMaxDynamicSharedMemorySize, SMEM_REC);

    prep_weights<<<896, 256>>>(W, U);
    x_convert<<<32768, 256>>>((const float4*)x);

    // Input conv: 2048 tiles of 128 rows
    gemm_conv<0><<<2048, 512, SMEM_IN>>>(nullptr, nullptr, nullptr, nullptr,
                                         nullptr, nullptr, 0);

    // t = 0: h0 = 0, so z = xz + b; pointwise only
    t0_pointwise<<<2048, 512>>>(out, b, gamma, beta, mean, var);

    for (int t = 1; t < 16; t++)
        gemm_conv<1><<<128, 512, SMEM_REC>>>(out, b, gamma, beta, mean, var, t);
}

// round 12
// speedup vs baseline: 6.5149x; 1.1441x over previous
#include <cuda_runtime.h>
#include <cuda_fp16.h>
#include <stdint.h>
#include <math.h>

// ---------------------------------------------------------------------------
// ConvLSTMBlock via ldmatrix + mma.sync (HMMA; harness PTX target sm_103).
//   input conv : GEMM M=262144, N=256, K=288(pad 320), A = im2col(x) stride2
//   recurrent  : GEMM M=16384,  N=256, K=576, persistent kernel, 15 steps
// R12: fixes R11's two correctness bugs --
//   (1) B is re-loaded every step (B-resident ping-pong was invalid: only 2
//       of 9 chunks fit in smem stages);
//   (2) h double-buffered across steps (halo reads from neighbor CTAs raced
//       with same-step h writes under a single buffer).
// Keeps: persistent recurrent kernel + grid barrier, register gate epilogue
// (strided gate-column warp mapping), c-state in smem.
// ---------------------------------------------------------------------------

// ---- device scratch (allocation-free rule) ----
__device__ __align__(1024) __half g_xzh[(size_t)64 * 4096 * 256];
__device__ __align__(1024) __half g_hf2[2][(size_t)4 * 4096 * 64];
__device__ __align__(1024) __half g_xh[(size_t)64 * 128 * 128 * 32];
__device__ __align__(1024) __half g_UH[256 * 576];
__device__ __align__(1024) __half g_WH[256 * 320];
__device__ volatile unsigned g_bar[16];

// ---- PTX helpers ----
__device__ __forceinline__ uint32_t s2u(const void* p) {
    uint32_t a;
    asm("{ .reg .u64 t; cvta.to.shared.u64 t, %1; cvt.u32.u64 %0, t; }"
        : "=r"(a) : "l"(p));
    return a;
}
__device__ __forceinline__ void cpa16(uint32_t dst, const void* src, uint32_t sz) {
    asm volatile("cp.async.cg.shared.global [%0], [%1], 16, %2;"
                 :: "r"(dst), "l"(src), "r"(sz));
}
__device__ __forceinline__ void cpcommit() {
    asm volatile("cp.async.commit_group;" ::: "memory");
}
template <int N> __device__ __forceinline__ void cpwait() {
    asm volatile("cp.async.wait_group %0;" :: "n"(N) : "memory");
}
__device__ __forceinline__ void ldm4(uint32_t* r, uint32_t addr) {
    asm volatile("ldmatrix.sync.aligned.m8n8.x4.shared.b16 {%0,%1,%2,%3}, [%4];"
                 : "=r"(r[0]), "=r"(r[1]), "=r"(r[2]), "=r"(r[3]) : "r"(addr));
}
__device__ __forceinline__ void mma16816(float* d, const uint32_t* a,
                                         uint32_t b0, uint32_t b1) {
    asm volatile(
        "mma.sync.aligned.m16n8k16.row.col.f32.f16.f16.f32 "
        "{%0,%1,%2,%3}, {%4,%5,%6,%7}, {%8,%9}, {%0,%1,%2,%3};"
        : "+f"(d[0]), "+f"(d[1]), "+f"(d[2]), "+f"(d[3])
        : "r"(a[0]), "r"(a[1]), "r"(a[2]), "r"(a[3]), "r"(b0), "r"(b1));
}

// ---- prep kernels ----
__global__ void prep_weights(const float* __restrict__ W, const float* __restrict__ U) {
    int idx = blockIdx.x * 256 + threadIdx.x;
    const int NU = 256 * 576;
    if (idx < NU) {
        int n = idx / 576, col = idx - n * 576;
        g_UH[idx] = __float2half_rn(U[(size_t)col * 256 + n]);
    } else {
        int j = idx - NU;
        if (j >= 256 * 320) return;
        int n = j / 320, col = j - n * 320;
        g_WH[j] = __float2half_rn((col < 288) ? W[(size_t)col * 256 + n] : 0.0f);
    }
}

__global__ void x_convert(const float4* __restrict__ x) {
    size_t i = (size_t)blockIdx.x * 256 + threadIdx.x;
    if (i >= (size_t)64 * 128 * 128 * 32 / 8) return;
    float4 v0 = x[2 * i], v1 = x[2 * i + 1];
    __half2 h0 = __floats2half2_rn(v0.x, v0.y);
    __half2 h1 = __floats2half2_rn(v0.z, v0.w);
    __half2 h2 = __floats2half2_rn(v1.x, v1.y);
    __half2 h3 = __floats2half2_rn(v1.z, v1.w);
    uint4 u;
    u.x = *reinterpret_cast<uint32_t*>(&h0);
    u.y = *reinterpret_cast<uint32_t*>(&h1);
    u.z = *reinterpret_cast<uint32_t*>(&h2);
    u.w = *reinterpret_cast<uint32_t*>(&h3);
    reinterpret_cast<uint4*>(g_xh)[i] = u;
}

__global__ void reset_bar() {
    if (threadIdx.x < 16) *((unsigned*)(g_bar + threadIdx.x)) = 0u;
}

// ---------------------------------------------------------------------------
// Input conv GEMM. CTA 128 rows x 256 cols, 16 warps (2M x 8N), warp N-tiles
// at strided gate columns {g8, g8+64, g8+128, g8+192}. K-chunk 64.
// ---------------------------------------------------------------------------
__global__ void __launch_bounds__(512, 1) gemm_in() {
    extern __shared__ char dsm[];
    const uint32_t smA = s2u(dsm);
    const uint32_t smB = smA + 32768;

    const int tid  = threadIdx.x;
    const int warp = tid >> 5;
    const int L    = tid & 31;
    const int tile = blockIdx.x;
    const int wm   = (warp >> 3) * 64;
    const int g8   = (warp & 7) * 8;

    const __half* aBase[2];
    uint32_t aDst[2];
    int aY[2], aX[2], aQh[2];
#pragma unroll
    for (int j = 0; j < 2; j++) {
        int i = tid + j * 512;
        int r = i >> 3, q = i & 7;
        int row = tile * 128 + r;
        int img = row >> 12, px = row & 4095;
        aY[j] = px >> 6; aX[j] = px & 63;
        aQh[j] = q >> 2;
        int ci0 = (q & 3) << 3;
        aBase[j] = g_xh + ((size_t)img << 19) + ci0;
        aDst[j] = (uint32_t)(r * 128 + ((q ^ (r & 7)) << 4));
    }
    const __half* bBase[4];
    uint32_t bDst[4];
#pragma unroll
    for (int j = 0; j < 4; j++) {
        int i = tid + j * 512;
        int n = i >> 3, q = i & 7;
        bBase[j] = g_WH + n * 320 + q * 8;
        bDst[j] = (uint32_t)(n * 128 + ((q ^ (n & 7)) << 4));
    }

    const int sub  = L >> 3;
    const int ri16 = ((sub & 1) << 3) + (L & 7);
    const int us   = sub >> 1;
    int aRowB[4], aRM[4];
#pragma unroll
    for (int mi = 0; mi < 4; mi++) {
        int r = wm + mi * 16 + ri16;
        aRowB[mi] = r * 128; aRM[mi] = r & 7;
    }
    int bRowB[2];
    const int bRM = L & 7;
#pragma unroll
    for (int jj = 0; jj < 2; jj++) {
        int n = g8 + jj * 128 + ((sub & 1) << 6) + (L & 7);
        bRowB[jj] = n * 128;
    }

    float d[4][4][4];
#pragma unroll
    for (int mi = 0; mi < 4; mi++)
#pragma unroll
        for (int n8 = 0; n8 < 4; n8++)
#pragma unroll
            for (int k = 0; k < 4; k++) d[mi][n8][k] = 0.0f;

    auto load_chunk = [&](int c, int s) {
#pragma unroll
        for (int j = 0; j < 2; j++) {
            int kpos = 2 * c + aQh[j];
            int ky = (kpos >= 6) ? 2 : ((kpos >= 3) ? 1 : 0);
            int kx = kpos - 3 * ky;
            int sy = aY[j] * 2 + ky;
            int sx = aX[j] * 2 + kx;
            bool ok = (kpos < 9) && (sy < 128) && (sx < 128);
            uint32_t off = ok ? (uint32_t)((((sy << 7) + sx) << 5)) : 0u;
            cpa16(smA + (uint32_t)s * 16384u + aDst[j], aBase[j] + off, ok ? 16u : 0u);
        }
#pragma unroll
        for (int j = 0; j < 4; j++)
            cpa16(smB + (uint32_t)s * 32768u + bDst[j], bBase[j] + (c << 6), 16u);
        cpcommit();
    };

    load_chunk(0, 0);

#pragma unroll 1
    for (int c = 0; c < 5; c++) {
        int s = c & 1;
        if (c + 1 < 5) { load_chunk(c + 1, s ^ 1); cpwait<1>(); }
        else           { cpwait<0>(); }
        __syncthreads();
        uint32_t sa = smA + (uint32_t)s * 16384u;
        uint32_t sb = smB + (uint32_t)s * 32768u;
#pragma unroll
        for (int kk = 0; kk < 4; kk++) {
            uint32_t a[4][4];
#pragma unroll
            for (int mi = 0; mi < 4; mi++)
                ldm4(a[mi], sa + aRowB[mi] + ((((kk << 1) | us) ^ aRM[mi]) << 4));
#pragma unroll
            for (int jj = 0; jj < 2; jj++) {
                uint32_t b[4];
                ldm4(b, sb + bRowB[jj] + ((((kk << 1) | us) ^ bRM) << 4));
#pragma unroll
                for (int mi = 0; mi < 4; mi++) {
                    mma16816(d[mi][2 * jj],     a[mi], b[0], b[2]);
                    mma16816(d[mi][2 * jj + 1], a[mi], b[1], b[3]);
                }
            }
        }
        __syncthreads();
    }

#pragma unroll
    for (int mi = 0; mi < 4; mi++) {
        int r0 = tile * 128 + wm + mi * 16 + (L >> 2);
#pragma unroll
        for (int n8 = 0; n8 < 4; n8++) {
            int col = g8 + n8 * 64 + ((L & 3) << 1);
            *reinterpret_cast<__half2*>(g_xzh + (size_t)r0 * 256 + col) =
                __floats2half2_rn(d[mi][n8][0], d[mi][n8][1]);
            *reinterpret_cast<__half2*>(g_xzh + (size_t)(r0 + 8) * 256 + col) =
                __floats2half2_rn(d[mi][n8][2], d[mi][n8][3]);
        }
    }
}

// ---------------------------------------------------------------------------
// Persistent recurrent kernel: 128 CTAs (one per M-tile), 16 timesteps.
// Grid barrier between steps; h double-buffered; c-state in smem.
// ---------------------------------------------------------------------------
__global__ void __launch_bounds__(512, 1) rec_loop(
    float* __restrict__ out, const float* __restrict__ bias,
    const float* __restrict__ gamma, const float* __restrict__ beta,
    const float* __restrict__ mean, const float* __restrict__ var)
{
    extern __shared__ char dsm[];
    const uint32_t smA = s2u(dsm);
    const uint32_t smB = smA + 32768;
    float* c_sm = reinterpret_cast<float*>(dsm + 98304);   // 128*65 floats

    const int tid  = threadIdx.x;
    const int warp = tid >> 5;
    const int L    = tid & 31;
    const int tile = blockIdx.x;
    const int wm   = (warp >> 3) * 64;
    const int g8   = (warp & 7) * 8;
    const int f0   = g8 + ((L & 3) << 1);

    // hoisted A-load geometry (offset within an h buffer)
    size_t aOff[2];
    uint32_t aDst[2];
    int aY[2], aX[2];
#pragma unroll
    for (int j = 0; j < 2; j++) {
        int i = tid + j * 512;
        int r = i >> 3, q = i & 7;
        int row = tile * 128 + r;
        int img = row >> 12, px = row & 4095;
        aY[j] = px >> 6; aX[j] = px & 63;
        aOff[j] = ((size_t)img << 18) + (q << 3);          // img*64*64*64 + ci0
        aDst[j] = (uint32_t)(r * 128 + ((q ^ (r & 7)) << 4));
    }
    const __half* bBase[4];
    uint32_t bDst[4];
#pragma unroll
    for (int j = 0; j < 4; j++) {
        int i = tid + j * 512;
        int n = i >> 3, q = i & 7;
        bBase[j] = g_UH + n * 576 + q * 8;
        bDst[j] = (uint32_t)(n * 128 + ((q ^ (n & 7)) << 4));
    }

    const int sub  = L >> 3;
    const int ri16 = ((sub & 1) << 3) + (L & 7);
    const int us   = sub >> 1;
    int aRowB[4], aRM[4];
#pragma unroll
    for (int mi = 0; mi < 4; mi++) {
        int r = wm + mi * 16 + ri16;
        aRowB[mi] = r * 128; aRM[mi] = r & 7;
    }
    int bRowB[2];
    const int bRM = L & 7;
#pragma unroll
    for (int jj = 0; jj < 2; jj++) {
        int n = g8 + jj * 128 + ((sub & 1) << 6) + (L & 7);
        bRowB[jj] = n * 128;
    }

    float bi[4][2];
#pragma unroll
    for (int g = 0; g < 4; g++) {
        bi[g][0] = bias[g * 64 + f0];
        bi[g][1] = bias[g * 64 + f0 + 1];
    }
    const float sc0 = gamma[f0] * rsqrtf(var[f0] + 1e-3f);
    const float sc1 = gamma[f0 + 1] * rsqrtf(var[f0 + 1] + 1e-3f);
    const float m0 = mean[f0], m1 = mean[f0 + 1];
    const float be0 = beta[f0], be1 = beta[f0 + 1];

    // ---- t = 0 pointwise (h0 = c0 = 0): z = xz + b ; writes h buffer 0 ----
#pragma unroll
    for (int mi = 0; mi < 4; mi++)
#pragma unroll
        for (int h2 = 0; h2 < 2; h2++) {
            int rloc = wm + mi * 16 + (L >> 2) + 8 * h2;
            int rg = tile * 128 + rloc;
            int b_ = rg >> 12, pix = rg & 4095;
            size_t xzb = ((((size_t)b_ * 16) * 4096 + pix) << 8) + f0;
            float2 xi = __half22float2(*(const __half2*)(g_xzh + xzb));
            float2 xg = __half22float2(*(const __half2*)(g_xzh + xzb + 128));
            float2 xo = __half22float2(*(const __half2*)(g_xzh + xzb + 192));
            float ig0 = __saturatef(0.2f * (xi.x + bi[0][0]) + 0.5f);
            float ig1 = __saturatef(0.2f * (xi.y + bi[0][1]) + 0.5f);
            float og0 = __saturatef(0.2f * (xo.x + bi[3][0]) + 0.5f);
            float og1 = __saturatef(0.2f * (xo.y + bi[3][1]) + 0.5f);
            float cn0 = ig0 * tanhf(xg.x + bi[2][0]);
            float cn1 = ig1 * tanhf(xg.y + bi[2][1]);
            float hn0 = og0 * tanhf(cn0);
            float hn1 = og1 * tanhf(cn1);
            c_sm[rloc * 65 + f0] = cn0;
            c_sm[rloc * 65 + f0 + 1] = cn1;
            *reinterpret_cast<__half2*>(g_hf2[0] + (size_t)rg * 64 + f0) =
                __floats2half2_rn(hn0, hn1);
            *reinterpret_cast<float2*>(out + ((((size_t)b_ * 16) * 4096 + pix) << 6) + f0) =
                make_float2((hn0 - m0) * sc0 + be0, (hn1 - m1) * sc1 + be1);
        }

    auto gbar = [&](int i) {
        __threadfence();
        __syncthreads();
        if (tid == 0) {
            atomicAdd((unsigned*)(g_bar + i), 1u);
            while (g_bar[i] < 128u) __nanosleep(64);
        }
        __syncthreads();
    };
    gbar(0);

    auto load_chunk = [&](const __half* aBuf, int c, int s) {
#pragma unroll
        for (int j = 0; j < 2; j++) {
            int ky = (c >= 6) ? 2 : ((c >= 3) ? 1 : 0);
            int kx = c - 3 * ky;
            int sy = aY[j] + ky - 1;
            int sx = aX[j] + kx - 1;
            bool ok = ((unsigned)sy < 64u) && ((unsigned)sx < 64u);
            uint32_t off = ok ? (uint32_t)((((sy << 6) + sx) << 6)) : 0u;
            cpa16(smA + (uint32_t)s * 16384u + aDst[j],
                  aBuf + aOff[j] + off, ok ? 16u : 0u);
        }
#pragma unroll
        for (int j = 0; j < 4; j++)
            cpa16(smB + (uint32_t)s * 32768u + bDst[j], bBase[j] + (c << 6), 16u);
        cpcommit();
    };

#pragma unroll 1
    for (int t = 1; t < 16; t++) {
        const __half* aBuf = g_hf2[(t + 1) & 1];   // read h_{t-1}
        __half* hw = g_hf2[t & 1];                 // write h_t

        float d[4][4][4];
#pragma unroll
        for (int mi = 0; mi < 4; mi++)
#pragma unroll
            for (int n8 = 0; n8 < 4; n8++)
#pragma unroll
                for (int k = 0; k < 4; k++) d[mi][n8][k] = 0.0f;

        load_chunk(aBuf, 0, 0);
#pragma unroll 1
        for (int c = 0; c < 9; c++) {
            int s = c & 1;
            if (c + 1 < 9) { load_chunk(aBuf, c + 1, s ^ 1); cpwait<1>(); }
            else           { cpwait<0>(); }
            __syncthreads();
            uint32_t sa = smA + (uint32_t)s * 16384u;
            uint32_t sb = smB + (uint32_t)s * 32768u;
#pragma unroll
            for (int kk = 0; kk < 4; kk++) {
                uint32_t a[4][4];
#pragma unroll
                for (int mi = 0; mi < 4; mi++)
                    ldm4(a[mi], sa + aRowB[mi] + ((((kk << 1) | us) ^ aRM[mi]) << 4));
#pragma unroll
                for (int jj = 0; jj < 2; jj++) {
                    uint32_t b[4];
                    ldm4(b, sb + bRowB[jj] + ((((kk << 1) | us) ^ bRM) << 4));
#pragma unroll
                    for (int mi = 0; mi < 4; mi++) {
                        mma16816(d[mi][2 * jj],     a[mi], b[0], b[2]);
                        mma16816(d[mi][2 * jj + 1], a[mi], b[1], b[3]);
                    }
                }
            }
            __syncthreads();
        }

        // register gate epilogue
#pragma unroll
        for (int mi = 0; mi < 4; mi++)
#pragma unroll
            for (int h2 = 0; h2 < 2; h2++) {
                int rloc = wm + mi * 16 + (L >> 2) + 8 * h2;
                int rg = tile * 128 + rloc;
                int b_ = rg >> 12, pix = rg & 4095;
                size_t xzb = ((((size_t)b_ * 16 + t) * 4096 + pix) << 8) + f0;
                float2 xi = __half22float2(*(const __half2*)(g_xzh + xzb));
                float2 xf = __half22float2(*(const __half2*)(g_xzh + xzb + 64));
                float2 xg = __half22float2(*(const __half2*)(g_xzh + xzb + 128));
                float2 xo = __half22float2(*(const __half2*)(g_xzh + xzb + 192));
                int k0 = 2 * h2;
                float zi0 = d[mi][0][k0] + xi.x + bi[0][0];
                float zf0 = d[mi][1][k0] + xf.x + bi[1][0];
                float zg0 = d[mi][2][k0] + xg.x + bi[2][0];
                float zo0 = d[mi][3][k0] + xo.x + bi[3][0];
                float zi1 = d[mi][0][k0 + 1] + xi.y + bi[0][1];
                float zf1 = d[mi][1][k0 + 1] + xf.y + bi[1][1];
                float zg1 = d[mi][2][k0 + 1] + xg.y + bi[2][1];
                float zo1 = d[mi][3][k0 + 1] + xo.y + bi[3][1];
                float ig0 = __saturatef(0.2f * zi0 + 0.5f);
                float fg0 = __saturatef(0.2f * zf0 + 0.5f);
                float og0 = __saturatef(0.2f * zo0 + 0.5f);
                float ig1 = __saturatef(0.2f * zi1 + 0.5f);
                float fg1 = __saturatef(0.2f * zf1 + 0.5f);
                float og1 = __saturatef(0.2f * zo1 + 0.5f);
                int ci = rloc * 65 + f0;
                float cn0 = fg0 * c_sm[ci] + ig0 * tanhf(zg0);
                float cn1 = fg1 * c_sm[ci + 1] + ig1 * tanhf(zg1);
                float hn0 = og0 * tanhf(cn0);
                float hn1 = og1 * tanhf(cn1);
                c_sm[ci] = cn0;
                c_sm[ci + 1] = cn1;
                *reinterpret_cast<__half2*>(hw + (size_t)rg * 64 + f0) =
                    __floats2half2_rn(hn0, hn1);
                *reinterpret_cast<float2*>(
                    out + ((((size_t)b_ * 16 + t) * 4096 + pix) << 6) + f0) =
                    make_float2((hn0 - m0) * sc0 + be0, (hn1 - m1) * sc1 + be1);
            }

        if (t < 15) gbar(t);
    }
}

extern "C" void kernel_launch(void* const* d_in, const int* in_sizes, int n_in,
                              void* d_out, int out_size)
{
    const float* x     = (const float*)d_in[0];
    const float* W     = (const float*)d_in[1];
    const float* U     = (const float*)d_in[2];
    const float* b     = (const float*)d_in[3];
    const float* gamma = (const float*)d_in[4];
    const float* beta  = (const float*)d_in[5];
    const float* mean  = (const float*)d_in[6];
    const float* var   = (const float*)d_in[7];
    float* out = (float*)d_out;

    const int SMEM_IN  = 2 * 16384 + 2 * 32768;          // 98304 B
    const int SMEM_REC = 98304 + 128 * 65 * 4;           // 131584 B

    cudaFuncSetAttribute((const void*)gemm_in,
                         cudaFuncAttributeMaxDynamicSharedMemorySize, SMEM_IN);
    cudaFuncSetAttribute((const void*)rec_loop,
                         cudaFuncAttributeMaxDynamicSharedMemorySize, SMEM_REC);

    prep_weights<<<896, 256>>>(W, U);
    x_convert<<<32768, 256>>>((const float4*)x);

    gemm_in<<<2048, 512, SMEM_IN>>>();

    reset_bar<<<1, 32>>>();
    rec_loop<<<128, 512, SMEM_REC>>>(out, b, gamma, beta, mean, var);
}

// round 14
// speedup vs baseline: 7.1574x; 1.0986x over previous
#include <cuda_runtime.h>
#include <cuda_fp16.h>
#include <stdint.h>
#include <math.h>

// ---------------------------------------------------------------------------
// ConvLSTMBlock via ldmatrix + mma.sync (HMMA; harness PTX target sm_103).
//   input conv : GEMM M=262144, N=256, K=288(pad 320), A = im2col(x) stride2
//   recurrent  : GEMM M=16384,  N=256, K=576, persistent kernel, 15 steps
// R13: single-sync pipeline (wait/sync/issue/MMA per chunk), xz prefetched
// to smem per step via cp.async (epilogue latency off critical path),
// reset_bar merged into prep_weights.
// ---------------------------------------------------------------------------

// ---- device scratch (allocation-free rule) ----
__device__ __align__(1024) __half g_xzh[(size_t)64 * 4096 * 256];
__device__ __align__(1024) __half g_hf2[2][(size_t)4 * 4096 * 64];
__device__ __align__(1024) __half g_xh[(size_t)64 * 128 * 128 * 32];
__device__ __align__(1024) __half g_UH[256 * 576];
__device__ __align__(1024) __half g_WH[256 * 320];
__device__ volatile unsigned g_bar[16];

// ---- PTX helpers ----
__device__ __forceinline__ uint32_t s2u(const void* p) {
    uint32_t a;
    asm("{ .reg .u64 t; cvta.to.shared.u64 t, %1; cvt.u32.u64 %0, t; }"
        : "=r"(a) : "l"(p));
    return a;
}
__device__ __forceinline__ void cpa16(uint32_t dst, const void* src, uint32_t sz) {
    asm volatile("cp.async.cg.shared.global [%0], [%1], 16, %2;"
                 :: "r"(dst), "l"(src), "r"(sz));
}
__device__ __forceinline__ void cpcommit() {
    asm volatile("cp.async.commit_group;" ::: "memory");
}
template <int N> __device__ __forceinline__ void cpwait() {
    asm volatile("cp.async.wait_group %0;" :: "n"(N) : "memory");
}
__device__ __forceinline__ void ldm4(uint32_t* r, uint32_t addr) {
    asm volatile("ldmatrix.sync.aligned.m8n8.x4.shared.b16 {%0,%1,%2,%3}, [%4];"
                 : "=r"(r[0]), "=r"(r[1]), "=r"(r[2]), "=r"(r[3]) : "r"(addr));
}
__device__ __forceinline__ void mma16816(float* d, const uint32_t* a,
                                         uint32_t b0, uint32_t b1) {
    asm volatile(
        "mma.sync.aligned.m16n8k16.row.col.f32.f16.f16.f32 "
        "{%0,%1,%2,%3}, {%4,%5,%6,%7}, {%8,%9}, {%0,%1,%2,%3};"
        : "+f"(d[0]), "+f"(d[1]), "+f"(d[2]), "+f"(d[3])
        : "r"(a[0]), "r"(a[1]), "r"(a[2]), "r"(a[3]), "r"(b0), "r"(b1));
}

// ---- prep kernels ----
__global__ void prep_weights(const float* __restrict__ W, const float* __restrict__ U) {
    int idx = blockIdx.x * 256 + threadIdx.x;
    if (idx < 16) *((unsigned*)(g_bar + idx)) = 0u;   // barrier reset
    const int NU = 256 * 576;
    if (idx < NU) {
        int n = idx / 576, col = idx - n * 576;
        g_UH[idx] = __float2half_rn(U[(size_t)col * 256 + n]);
    } else {
        int j = idx - NU;
        if (j >= 256 * 320) return;
        int n = j / 320, col = j - n * 320;
        g_WH[j] = __float2half_rn((col < 288) ? W[(size_t)col * 256 + n] : 0.0f);
    }
}

__global__ void x_convert(const float4* __restrict__ x) {
    size_t i = (size_t)blockIdx.x * 256 + threadIdx.x;
    if (i >= (size_t)64 * 128 * 128 * 32 / 8) return;
    float4 v0 = x[2 * i], v1 = x[2 * i + 1];
    __half2 h0 = __floats2half2_rn(v0.x, v0.y);
    __half2 h1 = __floats2half2_rn(v0.z, v0.w);
    __half2 h2 = __floats2half2_rn(v1.x, v1.y);
    __half2 h3 = __floats2half2_rn(v1.z, v1.w);
    uint4 u;
    u.x = *reinterpret_cast<uint32_t*>(&h0);
    u.y = *reinterpret_cast<uint32_t*>(&h1);
    u.z = *reinterpret_cast<uint32_t*>(&h2);
    u.w = *reinterpret_cast<uint32_t*>(&h3);
    reinterpret_cast<uint4*>(g_xh)[i] = u;
}

// ---------------------------------------------------------------------------
// Input conv GEMM. CTA 128 rows x 256 cols, 16 warps (2M x 8N), warp N-tiles
// at strided gate columns. K-chunk 64. Single sync per chunk.
// ---------------------------------------------------------------------------
__global__ void __launch_bounds__(512, 1) gemm_in() {
    extern __shared__ char dsm[];
    const uint32_t smA = s2u(dsm);
    const uint32_t smB = smA + 32768;

    const int tid  = threadIdx.x;
    const int warp = tid >> 5;
    const int L    = tid & 31;
    const int tile = blockIdx.x;
    const int wm   = (warp >> 3) * 64;
    const int g8   = (warp & 7) * 8;

    const __half* aBase[2];
    uint32_t aDst[2];
    int aY[2], aX[2], aQh[2];
#pragma unroll
    for (int j = 0; j < 2; j++) {
        int i = tid + j * 512;
        int r = i >> 3, q = i & 7;
        int row = tile * 128 + r;
        int img = row >> 12, px = row & 4095;
        aY[j] = px >> 6; aX[j] = px & 63;
        aQh[j] = q >> 2;
        int ci0 = (q & 3) << 3;
        aBase[j] = g_xh + ((size_t)img << 19) + ci0;
        aDst[j] = (uint32_t)(r * 128 + ((q ^ (r & 7)) << 4));
    }
    const __half* bBase[4];
    uint32_t bDst[4];
#pragma unroll
    for (int j = 0; j < 4; j++) {
        int i = tid + j * 512;
        int n = i >> 3, q = i & 7;
        bBase[j] = g_WH + n * 320 + q * 8;
        bDst[j] = (uint32_t)(n * 128 + ((q ^ (n & 7)) << 4));
    }

    const int sub  = L >> 3;
    const int ri16 = ((sub & 1) << 3) + (L & 7);
    const int us   = sub >> 1;
    int aRowB[4], aRM[4];
#pragma unroll
    for (int mi = 0; mi < 4; mi++) {
        int r = wm + mi * 16 + ri16;
        aRowB[mi] = r * 128; aRM[mi] = r & 7;
    }
    int bRowB[2];
    const int bRM = L & 7;
#pragma unroll
    for (int jj = 0; jj < 2; jj++) {
        int n = g8 + jj * 128 + ((sub & 1) << 6) + (L & 7);
        bRowB[jj] = n * 128;
    }

    float d[4][4][4];
#pragma unroll
    for (int mi = 0; mi < 4; mi++)
#pragma unroll
        for (int n8 = 0; n8 < 4; n8++)
#pragma unroll
            for (int k = 0; k < 4; k++) d[mi][n8][k] = 0.0f;

    auto load_chunk = [&](int c, int s) {
#pragma unroll
        for (int j = 0; j < 2; j++) {
            int kpos = 2 * c + aQh[j];
            int ky = (kpos >= 6) ? 2 : ((kpos >= 3) ? 1 : 0);
            int kx = kpos - 3 * ky;
            int sy = aY[j] * 2 + ky;
            int sx = aX[j] * 2 + kx;
            bool ok = (kpos < 9) && (sy < 128) && (sx < 128);
            uint32_t off = ok ? (uint32_t)((((sy << 7) + sx) << 5)) : 0u;
            cpa16(smA + (uint32_t)s * 16384u + aDst[j], aBase[j] + off, ok ? 16u : 0u);
        }
#pragma unroll
        for (int j = 0; j < 4; j++)
            cpa16(smB + (uint32_t)s * 32768u + bDst[j], bBase[j] + (c << 6), 16u);
        cpcommit();
    };

    load_chunk(0, 0);

#pragma unroll 1
    for (int c = 0; c < 5; c++) {
        int s = c & 1;
        cpwait<0>();
        __syncthreads();
        if (c + 1 < 5) load_chunk(c + 1, s ^ 1);
        uint32_t sa = smA + (uint32_t)s * 16384u;
        uint32_t sb = smB + (uint32_t)s * 32768u;
#pragma unroll
        for (int kk = 0; kk < 4; kk++) {
            uint32_t a[4][4];
#pragma unroll
            for (int mi = 0; mi < 4; mi++)
                ldm4(a[mi], sa + aRowB[mi] + ((((kk << 1) | us) ^ aRM[mi]) << 4));
#pragma unroll
            for (int jj = 0; jj < 2; jj++) {
                uint32_t b[4];
                ldm4(b, sb + bRowB[jj] + ((((kk << 1) | us) ^ bRM) << 4));
#pragma unroll
                for (int mi = 0; mi < 4; mi++) {
                    mma16816(d[mi][2 * jj],     a[mi], b[0], b[2]);
                    mma16816(d[mi][2 * jj + 1], a[mi], b[1], b[3]);
                }
            }
        }
    }

#pragma unroll
    for (int mi = 0; mi < 4; mi++) {
        int r0 = tile * 128 + wm + mi * 16 + (L >> 2);
#pragma unroll
        for (int n8 = 0; n8 < 4; n8++) {
            int col = g8 + n8 * 64 + ((L & 3) << 1);
            *reinterpret_cast<__half2*>(g_xzh + (size_t)r0 * 256 + col) =
                __floats2half2_rn(d[mi][n8][0], d[mi][n8][1]);
            *reinterpret_cast<__half2*>(g_xzh + (size_t)(r0 + 8) * 256 + col) =
                __floats2half2_rn(d[mi][n8][2], d[mi][n8][3]);
        }
    }
}

// ---------------------------------------------------------------------------
// Persistent recurrent kernel: 128 CTAs (one per M-tile), 16 timesteps.
// Grid barrier between steps; h double-buffered; c-state in smem; xz tile
// prefetched to smem (stride 264 halves = 528B rows, conflict-free).
// ---------------------------------------------------------------------------
__global__ void __launch_bounds__(512, 1) rec_loop(
    float* __restrict__ out, const float* __restrict__ bias,
    const float* __restrict__ gamma, const float* __restrict__ beta,
    const float* __restrict__ mean, const float* __restrict__ var)
{
    extern __shared__ char dsm[];
    const uint32_t smA = s2u(dsm);
    const uint32_t smB = smA + 32768;
    float*  c_sm = reinterpret_cast<float*>(dsm + 98304);     // 128*65 floats
    __half* zxs  = reinterpret_cast<__half*>(dsm + 131584);   // 128 x 264 halves
    const uint32_t smXZ = s2u(dsm) + 131584u;

    const int tid  = threadIdx.x;
    const int warp = tid >> 5;
    const int L    = tid & 31;
    const int tile = blockIdx.x;
    const int wm   = (warp >> 3) * 64;
    const int g8   = (warp & 7) * 8;
    const int f0   = g8 + ((L & 3) << 1);

    // hoisted A-load geometry (offset within an h buffer)
    size_t aOff[2];
    uint32_t aDst[2];
    int aY[2], aX[2];
#pragma unroll
    for (int j = 0; j < 2; j++) {
        int i = tid + j * 512;
        int r = i >> 3, q = i & 7;
        int row = tile * 128 + r;
        int img = row >> 12, px = row & 4095;
        aY[j] = px >> 6; aX[j] = px & 63;
        aOff[j] = ((size_t)img << 18) + (q << 3);
        aDst[j] = (uint32_t)(r * 128 + ((q ^ (r & 7)) << 4));
    }
    const __half* bBase[4];
    uint32_t bDst[4];
#pragma unroll
    for (int j = 0; j < 4; j++) {
        int i = tid + j * 512;
        int n = i >> 3, q = i & 7;
        bBase[j] = g_UH + n * 576 + q * 8;
        bDst[j] = (uint32_t)(n * 128 + ((q ^ (n & 7)) << 4));
    }
    // hoisted xz-prefetch geometry: 4096 16B units, 8 per thread
    size_t xzOff[8];
    uint32_t xzDst[8];
#pragma unroll
    for (int j = 0; j < 8; j++) {
        int u = tid + j * 512;
        int r = u >> 5, q = u & 31;
        int rg = tile * 128 + r;
        int b_ = rg >> 12, pix = rg & 4095;
        xzOff[j] = ((size_t)b_ << 24) + ((size_t)pix << 8) + (q << 3);
        xzDst[j] = (uint32_t)(r * 528 + q * 16);
    }

    const int sub  = L >> 3;
    const int ri16 = ((sub & 1) << 3) + (L & 7);
    const int us   = sub >> 1;
    int aRowB[4], aRM[4];
#pragma unroll
    for (int mi = 0; mi < 4; mi++) {
        int r = wm + mi * 16 + ri16;
        aRowB[mi] = r * 128; aRM[mi] = r & 7;
    }
    int bRowB[2];
    const int bRM = L & 7;
#pragma unroll
    for (int jj = 0; jj < 2; jj++) {
        int n = g8 + jj * 128 + ((sub & 1) << 6) + (L & 7);
        bRowB[jj] = n * 128;
    }

    float bi[4][2];
#pragma unroll
    for (int g = 0; g < 4; g++) {
        bi[g][0] = bias[g * 64 + f0];
        bi[g][1] = bias[g * 64 + f0 + 1];
    }
    const float sc0 = gamma[f0] * rsqrtf(var[f0] + 1e-3f);
    const float sc1 = gamma[f0 + 1] * rsqrtf(var[f0 + 1] + 1e-3f);
    const float m0 = mean[f0], m1 = mean[f0 + 1];
    const float be0 = beta[f0], be1 = beta[f0 + 1];

    // ---- t = 0 pointwise (h0 = c0 = 0): z = xz + b ; writes h buffer 0 ----
#pragma unroll
    for (int mi = 0; mi < 4; mi++)
#pragma unroll
        for (int h2 = 0; h2 < 2; h2++) {
            int rloc = wm + mi * 16 + (L >> 2) + 8 * h2;
            int rg = tile * 128 + rloc;
            int b_ = rg >> 12, pix = rg & 4095;
            size_t xzb = ((((size_t)b_ * 16) * 4096 + pix) << 8) + f0;
            float2 xi = __half22float2(*(const __half2*)(g_xzh + xzb));
            float2 xg = __half22float2(*(const __half2*)(g_xzh + xzb + 128));
            float2 xo = __half22float2(*(const __half2*)(g_xzh + xzb + 192));
            float ig0 = __saturatef(0.2f * (xi.x + bi[0][0]) + 0.5f);
            float ig1 = __saturatef(0.2f * (xi.y + bi[0][1]) + 0.5f);
            float og0 = __saturatef(0.2f * (xo.x + bi[3][0]) + 0.5f);
            float og1 = __saturatef(0.2f * (xo.y + bi[3][1]) + 0.5f);
            float cn0 = ig0 * tanhf(xg.x + bi[2][0]);
            float cn1 = ig1 * tanhf(xg.y + bi[2][1]);
            float hn0 = og0 * tanhf(cn0);
            float hn1 = og1 * tanhf(cn1);
            c_sm[rloc * 65 + f0] = cn0;
            c_sm[rloc * 65 + f0 + 1] = cn1;
            *reinterpret_cast<__half2*>(g_hf2[0] + (size_t)rg * 64 + f0) =
                __floats2half2_rn(hn0, hn1);
            *reinterpret_cast<float2*>(out + ((((size_t)b_ * 16) * 4096 + pix) << 6) + f0) =
                make_float2((hn0 - m0) * sc0 + be0, (hn1 - m1) * sc1 + be1);
        }

    auto gbar = [&](int i) {
        __threadfence();
        __syncthreads();
        if (tid == 0) {
            atomicAdd((unsigned*)(g_bar + i), 1u);
            while (g_bar[i] < 128u) __nanosleep(64);
        }
        __syncthreads();
    };
    gbar(0);

    auto load_chunk = [&](const __half* aBuf, int c, int s) {
#pragma unroll
        for (int j = 0; j < 2; j++) {
            int ky = (c >= 6) ? 2 : ((c >= 3) ? 1 : 0);
            int kx = c - 3 * ky;
            int sy = aY[j] + ky - 1;
            int sx = aX[j] + kx - 1;
            bool ok = ((unsigned)sy < 64u) && ((unsigned)sx < 64u);
            uint32_t off = ok ? (uint32_t)((((sy << 6) + sx) << 6)) : 0u;
            cpa16(smA + (uint32_t)s * 16384u + aDst[j],
                  aBuf + aOff[j] + off, ok ? 16u : 0u);
        }
#pragma unroll
        for (int j = 0; j < 4; j++)
            cpa16(smB + (uint32_t)s * 32768u + bDst[j], bBase[j] + (c << 6), 16u);
        cpcommit();
    };

#pragma unroll 1
    for (int t = 1; t < 16; t++) {
        const __half* aBuf = g_hf2[(t + 1) & 1];
        __half* hw = g_hf2[t & 1];

        float d[4][4][4];
#pragma unroll
        for (int mi = 0; mi < 4; mi++)
#pragma unroll
            for (int n8 = 0; n8 < 4; n8++)
#pragma unroll
                for (int k = 0; k < 4; k++) d[mi][n8][k] = 0.0f;

        load_chunk(aBuf, 0, 0);
        // xz tile prefetch (own group; completes during the 9 MMA chunks)
        {
            size_t tOff = (size_t)t << 20;
#pragma unroll
            for (int j = 0; j < 8; j++)
                cpa16(smXZ + xzDst[j], g_xzh + xzOff[j] + tOff, 16u);
            cpcommit();
        }

#pragma unroll 1
        for (int c = 0; c < 9; c++) {
            int s = c & 1;
            if (c == 0) cpwait<1>(); else cpwait<0>();
            __syncthreads();
            if (c + 1 < 9) load_chunk(aBuf, c + 1, s ^ 1);
            uint32_t sa = smA + (uint32_t)s * 16384u;
            uint32_t sb = smB + (uint32_t)s * 32768u;
#pragma unroll
            for (int kk = 0; kk < 4; kk++) {
                uint32_t a[4][4];
#pragma unroll
                for (int mi = 0; mi < 4; mi++)
                    ldm4(a[mi], sa + aRowB[mi] + ((((kk << 1) | us) ^ aRM[mi]) << 4));
#pragma unroll
                for (int jj = 0; jj < 2; jj++) {
                    uint32_t b[4];
                    ldm4(b, sb + bRowB[jj] + ((((kk << 1) | us) ^ bRM) << 4));
#pragma unroll
                    for (int mi = 0; mi < 4; mi++) {
                        mma16816(d[mi][2 * jj],     a[mi], b[0], b[2]);
                        mma16816(d[mi][2 * jj + 1], a[mi], b[1], b[3]);
                    }
                }
            }
        }

        // register gate epilogue (xz from smem, conflict-free)
#pragma unroll
        for (int mi = 0; mi < 4; mi++)
#pragma unroll
            for (int h2 = 0; h2 < 2; h2++) {
                int rloc = wm + mi * 16 + (L >> 2) + 8 * h2;
                int rg = tile * 128 + rloc;
                int b_ = rg >> 12, pix = rg & 4095;
                const __half* zr = zxs + rloc * 264 + f0;
                float2 xi = __half22float2(*(const __half2*)(zr));
                float2 xf = __half22float2(*(const __half2*)(zr + 64));
                float2 xg = __half22float2(*(const __half2*)(zr + 128));
                float2 xo = __half22float2(*(const __half2*)(zr + 192));
                int k0 = 2 * h2;
                float zi0 = d[mi][0][k0] + xi.x + bi[0][0];
                float zf0 = d[mi][1][k0] + xf.x + bi[1][0];
                float zg0 = d[mi][2][k0] + xg.x + bi[2][0];
                float zo0 = d[mi][3][k0] + xo.x + bi[3][0];
                float zi1 = d[mi][0][k0 + 1] + xi.y + bi[0][1];
                float zf1 = d[mi][1][k0 + 1] + xf.y + bi[1][1];
                float zg1 = d[mi][2][k0 + 1] + xg.y + bi[2][1];
                float zo1 = d[mi][3][k0 + 1] + xo.y + bi[3][1];
                float ig0 = __saturatef(0.2f * zi0 + 0.5f);
                float fg0 = __saturatef(0.2f * zf0 + 0.5f);
                float og0 = __saturatef(0.2f * zo0 + 0.5f);
                float ig1 = __saturatef(0.2f * zi1 + 0.5f);
                float fg1 = __saturatef(0.2f * zf1 + 0.5f);
                float og1 = __saturatef(0.2f * zo1 + 0.5f);
                int ci = rloc * 65 + f0;
                float cn0 = fg0 * c_sm[ci] + ig0 * tanhf(zg0);
                float cn1 = fg1 * c_sm[ci + 1] + ig1 * tanhf(zg1);
                float hn0 = og0 * tanhf(cn0);
                float hn1 = og1 * tanhf(cn1);
                c_sm[ci] = cn0;
                c_sm[ci + 1] = cn1;
                *reinterpret_cast<__half2*>(hw + (size_t)rg * 64 + f0) =
                    __floats2half2_rn(hn0, hn1);
                *reinterpret_cast<float2*>(
                    out + ((((size_t)b_ * 16 + t) * 4096 + pix) << 6) + f0) =
                    make_float2((hn0 - m0) * sc0 + be0, (hn1 - m1) * sc1 + be1);
            }

        if (t < 15) gbar(t);
    }
}

extern "C" void kernel_launch(void* const* d_in, const int* in_sizes, int n_in,
                              void* d_out, int out_size)
{
    const float* x     = (const float*)d_in[0];
    const float* W     = (const float*)d_in[1];
    const float* U     = (const float*)d_in[2];
    const float* b     = (const float*)d_in[3];
    const float* gamma = (const float*)d_in[4];
    const float* beta  = (const float*)d_in[5];
    const float* mean  = (const float*)d_in[6];
    const float* var   = (const float*)d_in[7];
    float* out = (float*)d_out;

    const int SMEM_IN  = 2 * 16384 + 2 * 32768;                 // 98304 B
    const int SMEM_REC = 98304 + 128 * 65 * 4 + 128 * 264 * 2;  // 199168 B

    cudaFuncSetAttribute((const void*)gemm_in,
                         cudaFuncAttributeMaxDynamicSharedMemorySize, SMEM_IN);
    cudaFuncSetAttribute((const void*)rec_loop,
                         cudaFuncAttributeMaxDynamicSharedMemorySize, SMEM_REC);

    prep_weights<<<896, 256>>>(W, U);
    x_convert<<<32768, 256>>>((const float4*)x);

    gemm_in<<<2048, 512, SMEM_IN>>>();

    rec_loop<<<128, 512, SMEM_REC>>>(out, b, gamma, beta, mean, var);
}

// round 15
// speedup vs baseline: 7.3454x; 1.0263x over previous
#include <cuda_runtime.h>
#include <cuda_fp16.h>
#include <stdint.h>
#include <math.h>

// ---------------------------------------------------------------------------
// ConvLSTMBlock via ldmatrix + mma.sync (HMMA; harness PTX target sm_103).
//   input conv : GEMM M=262144, N=256, K=288(pad 320), A = im2col(x) stride2
//   recurrent  : GEMM M=16384,  N=256, K=576, persistent kernel, 15 steps
// R15: fully-unrolled K-chunk loops (constant-folds gather math, CSEs ldm
// addresses; fixes alu=33% issue pollution), chunk order {3,4,5,0,1,2,6,7,8}
// so next-step chunk0 + xz prefetch issue BEFORE the grid barrier (ky=1
// chunks read only rows owned by this CTA).
// ---------------------------------------------------------------------------

// ---- device scratch (allocation-free rule) ----
__device__ __align__(1024) __half g_xzh[(size_t)64 * 4096 * 256];
__device__ __align__(1024) __half g_hf2[2][(size_t)4 * 4096 * 64];
__device__ __align__(1024) __half g_xh[(size_t)64 * 128 * 128 * 32];
__device__ __align__(1024) __half g_UH[256 * 576];
__device__ __align__(1024) __half g_WH[256 * 320];
__device__ volatile unsigned g_bar[16];

// ---- PTX helpers ----
__device__ __forceinline__ uint32_t s2u(const void* p) {
    uint32_t a;
    asm("{ .reg .u64 t; cvta.to.shared.u64 t, %1; cvt.u32.u64 %0, t; }"
        : "=r"(a) : "l"(p));
    return a;
}
__device__ __forceinline__ void cpa16(uint32_t dst, const void* src, uint32_t sz) {
    asm volatile("cp.async.cg.shared.global [%0], [%1], 16, %2;"
                 :: "r"(dst), "l"(src), "r"(sz));
}
__device__ __forceinline__ void cpcommit() {
    asm volatile("cp.async.commit_group;" ::: "memory");
}
template <int N> __device__ __forceinline__ void cpwait() {
    asm volatile("cp.async.wait_group %0;" :: "n"(N) : "memory");
}
__device__ __forceinline__ void ldm4(uint32_t* r, uint32_t addr) {
    asm volatile("ldmatrix.sync.aligned.m8n8.x4.shared.b16 {%0,%1,%2,%3}, [%4];"
                 : "=r"(r[0]), "=r"(r[1]), "=r"(r[2]), "=r"(r[3]) : "r"(addr));
}
__device__ __forceinline__ void mma16816(float* d, const uint32_t* a,
                                         uint32_t b0, uint32_t b1) {
    asm volatile(
        "mma.sync.aligned.m16n8k16.row.col.f32.f16.f16.f32 "
        "{%0,%1,%2,%3}, {%4,%5,%6,%7}, {%8,%9}, {%0,%1,%2,%3};"
        : "+f"(d[0]), "+f"(d[1]), "+f"(d[2]), "+f"(d[3])
        : "r"(a[0]), "r"(a[1]), "r"(a[2]), "r"(a[3]), "r"(b0), "r"(b1));
}

// ---- prep kernels ----
__global__ void prep_weights(const float* __restrict__ W, const float* __restrict__ U) {
    int idx = blockIdx.x * 256 + threadIdx.x;
    if (idx < 16) *((unsigned*)(g_bar + idx)) = 0u;
    const int NU = 256 * 576;
    if (idx < NU) {
        int n = idx / 576, col = idx - n * 576;
        g_UH[idx] = __float2half_rn(U[(size_t)col * 256 + n]);
    } else {
        int j = idx - NU;
        if (j >= 256 * 320) return;
        int n = j / 320, col = j - n * 320;
        g_WH[j] = __float2half_rn((col < 288) ? W[(size_t)col * 256 + n] : 0.0f);
    }
}

__global__ void x_convert(const float4* __restrict__ x) {
    size_t i = (size_t)blockIdx.x * 256 + threadIdx.x;
    if (i >= (size_t)64 * 128 * 128 * 32 / 8) return;
    float4 v0 = x[2 * i], v1 = x[2 * i + 1];
    __half2 h0 = __floats2half2_rn(v0.x, v0.y);
    __half2 h1 = __floats2half2_rn(v0.z, v0.w);
    __half2 h2 = __floats2half2_rn(v1.x, v1.y);
    __half2 h3 = __floats2half2_rn(v1.z, v1.w);
    uint4 u;
    u.x = *reinterpret_cast<uint32_t*>(&h0);
    u.y = *reinterpret_cast<uint32_t*>(&h1);
    u.z = *reinterpret_cast<uint32_t*>(&h2);
    u.w = *reinterpret_cast<uint32_t*>(&h3);
    reinterpret_cast<uint4*>(g_xh)[i] = u;
}

// ---------------------------------------------------------------------------
// Input conv GEMM. CTA 128 rows x 256 cols, 16 warps (2M x 8N). K-chunk 64,
// 5 chunks fully unrolled, single sync per chunk.
// ---------------------------------------------------------------------------
__global__ void __launch_bounds__(512, 1) gemm_in() {
    extern __shared__ char dsm[];
    const uint32_t smA = s2u(dsm);
    const uint32_t smB = smA + 32768;

    const int tid  = threadIdx.x;
    const int warp = tid >> 5;
    const int L    = tid & 31;
    const int tile = blockIdx.x;
    const int wm   = (warp >> 3) * 64;
    const int g8   = (warp & 7) * 8;

    const __half* aBase[2];
    uint32_t aDst[2];
    int aY[2], aX[2], aQh[2];
#pragma unroll
    for (int j = 0; j < 2; j++) {
        int i = tid + j * 512;
        int r = i >> 3, q = i & 7;
        int row = tile * 128 + r;
        int img = row >> 12, px = row & 4095;
        aY[j] = px >> 6; aX[j] = px & 63;
        aQh[j] = q >> 2;
        int ci0 = (q & 3) << 3;
        aBase[j] = g_xh + ((size_t)img << 19) + ci0;
        aDst[j] = (uint32_t)(r * 128 + ((q ^ (r & 7)) << 4));
    }
    const __half* bBase[4];
    uint32_t bDst[4];
#pragma unroll
    for (int j = 0; j < 4; j++) {
        int i = tid + j * 512;
        int n = i >> 3, q = i & 7;
        bBase[j] = g_WH + n * 320 + q * 8;
        bDst[j] = (uint32_t)(n * 128 + ((q ^ (n & 7)) << 4));
    }

    const int sub  = L >> 3;
    const int ri16 = ((sub & 1) << 3) + (L & 7);
    const int us   = sub >> 1;
    uint32_t kksel[4];
#pragma unroll
    for (int kk = 0; kk < 4; kk++) kksel[kk] = (uint32_t)(((kk << 1) | us) << 4);

    uint32_t aRow[4], bRow[2];
#pragma unroll
    for (int mi = 0; mi < 4; mi++) {
        int r = wm + mi * 16 + ri16;
        aRow[mi] = (uint32_t)(r * 128) | 0x80000000u;   // marker unused; plain
        aRow[mi] = (uint32_t)(r * 128);
    }
    uint32_t aRMs[4];
#pragma unroll
    for (int mi = 0; mi < 4; mi++) {
        int r = wm + mi * 16 + ri16;
        aRMs[mi] = (uint32_t)((r & 7) << 4);
    }
    uint32_t bRMs = (uint32_t)((L & 7) << 4);
#pragma unroll
    for (int jj = 0; jj < 2; jj++) {
        int n = g8 + jj * 128 + ((sub & 1) << 6) + (L & 7);
        bRow[jj] = (uint32_t)(n * 128);
    }

    float d[4][4][4];
#pragma unroll
    for (int mi = 0; mi < 4; mi++)
#pragma unroll
        for (int n8 = 0; n8 < 4; n8++)
#pragma unroll
            for (int k = 0; k < 4; k++) d[mi][n8][k] = 0.0f;

    auto load_chunk = [&](int c, int s) {
#pragma unroll
        for (int j = 0; j < 2; j++) {
            int kpos = 2 * c + aQh[j];
            int ky = (kpos >= 6) ? 2 : ((kpos >= 3) ? 1 : 0);
            int kx = kpos - 3 * ky;
            int sy = aY[j] * 2 + ky;
            int sx = aX[j] * 2 + kx;
            bool ok = (kpos < 9) && (sy < 128) && (sx < 128);
            uint32_t off = ok ? (uint32_t)((((sy << 7) + sx) << 5)) : 0u;
            cpa16(smA + (uint32_t)s * 16384u + aDst[j], aBase[j] + off, ok ? 16u : 0u);
        }
#pragma unroll
        for (int j = 0; j < 4; j++)
            cpa16(smB + (uint32_t)s * 32768u + bDst[j], bBase[j] + (c << 6), 16u);
        cpcommit();
    };

    load_chunk(0, 0);

#pragma unroll
    for (int c = 0; c < 5; c++) {
        int s = c & 1;
        cpwait<0>();
        __syncthreads();
        if (c + 1 < 5) load_chunk(c + 1, s ^ 1);
        uint32_t sa = smA + (uint32_t)s * 16384u;
        uint32_t sb = smB + (uint32_t)s * 32768u;
#pragma unroll
        for (int kk = 0; kk < 4; kk++) {
            uint32_t a[4][4];
#pragma unroll
            for (int mi = 0; mi < 4; mi++)
                ldm4(a[mi], sa + aRow[mi] + (kksel[kk] ^ aRMs[mi]));
#pragma unroll
            for (int jj = 0; jj < 2; jj++) {
                uint32_t b[4];
                ldm4(b, sb + bRow[jj] + (kksel[kk] ^ bRMs));
#pragma unroll
                for (int mi = 0; mi < 4; mi++) {
                    mma16816(d[mi][2 * jj],     a[mi], b[0], b[2]);
                    mma16816(d[mi][2 * jj + 1], a[mi], b[1], b[3]);
                }
            }
        }
    }

#pragma unroll
    for (int mi = 0; mi < 4; mi++) {
        int r0 = tile * 128 + wm + mi * 16 + (L >> 2);
#pragma unroll
        for (int n8 = 0; n8 < 4; n8++) {
            int col = g8 + n8 * 64 + ((L & 3) << 1);
            *reinterpret_cast<__half2*>(g_xzh + (size_t)r0 * 256 + col) =
                __floats2half2_rn(d[mi][n8][0], d[mi][n8][1]);
            *reinterpret_cast<__half2*>(g_xzh + (size_t)(r0 + 8) * 256 + col) =
                __floats2half2_rn(d[mi][n8][2], d[mi][n8][3]);
        }
    }
}

// ---------------------------------------------------------------------------
// Persistent recurrent kernel: 128 CTAs (one per M-tile), 16 timesteps.
// Grid barrier between steps; h double-buffered; c-state in smem; xz tile
// in smem (stride 264 halves). Chunk order {3,4,5,0,1,2,6,7,8}: chunk 3
// (ky=1, own rows only) + xz prefetched BEFORE the barrier.
// ---------------------------------------------------------------------------
__global__ void __launch_bounds__(512, 1) rec_loop(
    float* __restrict__ out, const float* __restrict__ bias,
    const float* __restrict__ gamma, const float* __restrict__ beta,
    const float* __restrict__ mean, const float* __restrict__ var)
{
    extern __shared__ char dsm[];
    const uint32_t smA = s2u(dsm);
    const uint32_t smB = smA + 32768;
    float*  c_sm = reinterpret_cast<float*>(dsm + 98304);     // 128*65 floats
    __half* zxs  = reinterpret_cast<__half*>(dsm + 131584);   // 128 x 264 halves
    const uint32_t smXZ = s2u(dsm) + 131584u;

    const int tid  = threadIdx.x;
    const int warp = tid >> 5;
    const int L    = tid & 31;
    const int tile = blockIdx.x;
    const int wm   = (warp >> 3) * 64;
    const int g8   = (warp & 7) * 8;
    const int f0   = g8 + ((L & 3) << 1);

    size_t aOff[2];
    uint32_t aDst[2];
    int aY[2], aX[2];
#pragma unroll
    for (int j = 0; j < 2; j++) {
        int i = tid + j * 512;
        int r = i >> 3, q = i & 7;
        int row = tile * 128 + r;
        int img = row >> 12, px = row & 4095;
        aY[j] = px >> 6; aX[j] = px & 63;
        aOff[j] = ((size_t)img << 18) + (q << 3);
        aDst[j] = (uint32_t)(r * 128 + ((q ^ (r & 7)) << 4));
    }
    const __half* bBase[4];
    uint32_t bDst[4];
#pragma unroll
    for (int j = 0; j < 4; j++) {
        int i = tid + j * 512;
        int n = i >> 3, q = i & 7;
        bBase[j] = g_UH + n * 576 + q * 8;
        bDst[j] = (uint32_t)(n * 128 + ((q ^ (n & 7)) << 4));
    }
    size_t xzOff[8];
    uint32_t xzDst[8];
#pragma unroll
    for (int j = 0; j < 8; j++) {
        int u = tid + j * 512;
        int r = u >> 5, q = u & 31;
        int rg = tile * 128 + r;
        int b_ = rg >> 12, pix = rg & 4095;
        xzOff[j] = ((size_t)b_ << 24) + ((size_t)pix << 8) + (q << 3);
        xzDst[j] = (uint32_t)(r * 528 + q * 16);
    }

    const int sub  = L >> 3;
    const int ri16 = ((sub & 1) << 3) + (L & 7);
    const int us   = sub >> 1;
    uint32_t kksel[4];
#pragma unroll
    for (int kk = 0; kk < 4; kk++) kksel[kk] = (uint32_t)(((kk << 1) | us) << 4);

    uint32_t aRow[4], aRMs[4], bRow[2];
#pragma unroll
    for (int mi = 0; mi < 4; mi++) {
        int r = wm + mi * 16 + ri16;
        aRow[mi] = (uint32_t)(r * 128);
        aRMs[mi] = (uint32_t)((r & 7) << 4);
    }
    uint32_t bRMs = (uint32_t)((L & 7) << 4);
#pragma unroll
    for (int jj = 0; jj < 2; jj++) {
        int n = g8 + jj * 128 + ((sub & 1) << 6) + (L & 7);
        bRow[jj] = (uint32_t)(n * 128);
    }

    float bi[4][2];
#pragma unroll
    for (int g = 0; g < 4; g++) {
        bi[g][0] = bias[g * 64 + f0];
        bi[g][1] = bias[g * 64 + f0 + 1];
    }
    const float sc0 = gamma[f0] * rsqrtf(var[f0] + 1e-3f);
    const float sc1 = gamma[f0 + 1] * rsqrtf(var[f0 + 1] + 1e-3f);
    const float m0 = mean[f0], m1 = mean[f0 + 1];
    const float be0 = beta[f0], be1 = beta[f0 + 1];

    auto load_chunk = [&](const __half* aBuf, int c, int s) {
#pragma unroll
        for (int j = 0; j < 2; j++) {
            int ky = (c >= 6) ? 2 : ((c >= 3) ? 1 : 0);
            int kx = c - 3 * ky;
            int sy = aY[j] + ky - 1;
            int sx = aX[j] + kx - 1;
            bool ok = ((unsigned)sy < 64u) && ((unsigned)sx < 64u);
            uint32_t off = ok ? (uint32_t)((((sy << 6) + sx) << 6)) : 0u;
            cpa16(smA + (uint32_t)s * 16384u + aDst[j],
                  aBuf + aOff[j] + off, ok ? 16u : 0u);
        }
#pragma unroll
        for (int j = 0; j < 4; j++)
            cpa16(smB + (uint32_t)s * 32768u + bDst[j], bBase[j] + (c << 6), 16u);
        cpcommit();
    };
    auto prefetch_xz = [&](int t) {
        size_t tOff = (size_t)t << 20;
#pragma unroll
        for (int j = 0; j < 8; j++)
            cpa16(smXZ + xzDst[j], g_xzh + xzOff[j] + tOff, 16u);
        cpcommit();
    };

    // ---- t = 0 pointwise (h0 = c0 = 0): z = xz + b ; writes h buffer 0 ----
#pragma unroll
    for (int mi = 0; mi < 4; mi++)
#pragma unroll
        for (int h2 = 0; h2 < 2; h2++) {
            int rloc = wm + mi * 16 + (L >> 2) + 8 * h2;
            int rg = tile * 128 + rloc;
            int b_ = rg >> 12, pix = rg & 4095;
            size_t xzb = ((((size_t)b_ * 16) * 4096 + pix) << 8) + f0;
            float2 xi = __half22float2(*(const __half2*)(g_xzh + xzb));
            float2 xg = __half22float2(*(const __half2*)(g_xzh + xzb + 128));
            float2 xo = __half22float2(*(const __half2*)(g_xzh + xzb + 192));
            float ig0 = __saturatef(0.2f * (xi.x + bi[0][0]) + 0.5f);
            float ig1 = __saturatef(0.2f * (xi.y + bi[0][1]) + 0.5f);
            float og0 = __saturatef(0.2f * (xo.x + bi[3][0]) + 0.5f);
            float og1 = __saturatef(0.2f * (xo.y + bi[3][1]) + 0.5f);
            float cn0 = ig0 * tanhf(xg.x + bi[2][0]);
            float cn1 = ig1 * tanhf(xg.y + bi[2][1]);
            float hn0 = og0 * tanhf(cn0);
            float hn1 = og1 * tanhf(cn1);
            c_sm[rloc * 65 + f0] = cn0;
            c_sm[rloc * 65 + f0 + 1] = cn1;
            *reinterpret_cast<__half2*>(g_hf2[0] + (size_t)rg * 64 + f0) =
                __floats2half2_rn(hn0, hn1);
            *reinterpret_cast<float2*>(out + ((((size_t)b_ * 16) * 4096 + pix) << 6) + f0) =
                make_float2((hn0 - m0) * sc0 + be0, (hn1 - m1) * sc1 + be1);
        }

    auto gbar = [&](int i) {
        __threadfence();
        __syncthreads();
        if (tid == 0) {
            atomicAdd((unsigned*)(g_bar + i), 1u);
            while (g_bar[i] < 128u) __nanosleep(64);
        }
        __syncthreads();
    };

    // pre-barrier prefetch for t=1: chunk 3 (own rows) + xz tile
    __syncthreads();
    load_chunk(g_hf2[0], 3, 0);
    prefetch_xz(1);
    gbar(0);

    const int ORD[9] = {3, 4, 5, 0, 1, 2, 6, 7, 8};

#pragma unroll 1
    for (int t = 1; t < 16; t++) {
        const __half* aBuf = g_hf2[(t + 1) & 1];
        __half* hw = g_hf2[t & 1];

        float d[4][4][4];
#pragma unroll
        for (int mi = 0; mi < 4; mi++)
#pragma unroll
            for (int n8 = 0; n8 < 4; n8++)
#pragma unroll
                for (int k = 0; k < 4; k++) d[mi][n8][k] = 0.0f;

#pragma unroll
        for (int i = 0; i < 9; i++) {
            int s = i & 1;
            if (i == 0) cpwait<1>(); else cpwait<0>();
            __syncthreads();
            if (i + 1 < 9) load_chunk(aBuf, ORD[i + 1], (i + 1) & 1);
            uint32_t sa = smA + (uint32_t)s * 16384u;
            uint32_t sb = smB + (uint32_t)s * 32768u;
#pragma unroll
            for (int kk = 0; kk < 4; kk++) {
                uint32_t a[4][4];
#pragma unroll
                for (int mi = 0; mi < 4; mi++)
                    ldm4(a[mi], sa + aRow[mi] + (kksel[kk] ^ aRMs[mi]));
#pragma unroll
                for (int jj = 0; jj < 2; jj++) {
                    uint32_t b[4];
                    ldm4(b, sb + bRow[jj] + (kksel[kk] ^ bRMs));
#pragma unroll
                    for (int mi = 0; mi < 4; mi++) {
                        mma16816(d[mi][2 * jj],     a[mi], b[0], b[2]);
                        mma16816(d[mi][2 * jj + 1], a[mi], b[1], b[3]);
                    }
                }
            }
        }

        // register gate epilogue (xz from smem, conflict-free)
#pragma unroll
        for (int mi = 0; mi < 4; mi++)
#pragma unroll
            for (int h2 = 0; h2 < 2; h2++) {
                int rloc = wm + mi * 16 + (L >> 2) + 8 * h2;
                int rg = tile * 128 + rloc;
                int b_ = rg >> 12, pix = rg & 4095;
                const __half* zr = zxs + rloc * 264 + f0;
                float2 xi = __half22float2(*(const __half2*)(zr));
                float2 xf = __half22float2(*(const __half2*)(zr + 64));
                float2 xg = __half22float2(*(const __half2*)(zr + 128));
                float2 xo = __half22float2(*(const __half2*)(zr + 192));
                int k0 = 2 * h2;
                float zi0 = d[mi][0][k0] + xi.x + bi[0][0];
                float zf0 = d[mi][1][k0] + xf.x + bi[1][0];
                float zg0 = d[mi][2][k0] + xg.x + bi[2][0];
                float zo0 = d[mi][3][k0] + xo.x + bi[3][0];
                float zi1 = d[mi][0][k0 + 1] + xi.y + bi[0][1];
                float zf1 = d[mi][1][k0 + 1] + xf.y + bi[1][1];
                float zg1 = d[mi][2][k0 + 1] + xg.y + bi[2][1];
                float zo1 = d[mi][3][k0 + 1] + xo.y + bi[3][1];
                float ig0 = __saturatef(0.2f * zi0 + 0.5f);
                float fg0 = __saturatef(0.2f * zf0 + 0.5f);
                float og0 = __saturatef(0.2f * zo0 + 0.5f);
                float ig1 = __saturatef(0.2f * zi1 + 0.5f);
                float fg1 = __saturatef(0.2f * zf1 + 0.5f);
                float og1 = __saturatef(0.2f * zo1 + 0.5f);
                int ci = rloc * 65 + f0;
                float cn0 = fg0 * c_sm[ci] + ig0 * tanhf(zg0);
                float cn1 = fg1 * c_sm[ci + 1] + ig1 * tanhf(zg1);
                float hn0 = og0 * tanhf(cn0);
                float hn1 = og1 * tanhf(cn1);
                c_sm[ci] = cn0;
                c_sm[ci + 1] = cn1;
                *reinterpret_cast<__half2*>(hw + (size_t)rg * 64 + f0) =
                    __floats2half2_rn(hn0, hn1);
                *reinterpret_cast<float2*>(
                    out + ((((size_t)b_ * 16 + t) * 4096 + pix) << 6) + f0) =
                    make_float2((hn0 - m0) * sc0 + be0, (hn1 - m1) * sc1 + be1);
            }

        if (t < 15) {
            __syncthreads();              // h writes + zxs reads complete
            load_chunk(hw, 3, 0);         // next step chunk 3 (own rows)
            prefetch_xz(t + 1);
            gbar(t);
        }
    }
}

extern "C" void kernel_launch(void* const* d_in, const int* in_sizes, int n_in,
                              void* d_out, int out_size)
{
    const float* x     = (const float*)d_in[0];
    const float* W     = (const float*)d_in[1];
    const float* U     = (const float*)d_in[2];
    const float* b     = (const float*)d_in[3];
    const float* gamma = (const float*)d_in[4];
    const float* beta  = (const float*)d_in[5];
    const float* mean  = (const float*)d_in[6];
    const float* var   = (const float*)d_in[7];
    float* out = (float*)d_out;

    const int SMEM_IN  = 2 * 16384 + 2 * 32768;                 // 98304 B
    const int SMEM_REC = 98304 + 128 * 65 * 4 + 128 * 264 * 2;  // 199168 B

    cudaFuncSetAttribute((const void*)gemm_in,
                         cudaFuncAttributeMaxDynamicSharedMemorySize, SMEM_IN);
    cudaFuncSetAttribute((const void*)rec_loop,
                         cudaFuncAttributeMaxDynamicSharedMemorySize, SMEM_REC);

    prep_weights<<<896, 256>>>(W, U);
    x_convert<<<32768, 256>>>((const float4*)x);

    gemm_in<<<2048, 512, SMEM_IN>>>();

    rec_loop<<<128, 512, SMEM_REC>>>(out, b, gamma, beta, mean, var);
}

// round 17
// speedup vs baseline: 7.5736x; 1.0311x over previous
#include <cuda_runtime.h>
#include <cuda_fp16.h>
#include <stdint.h>
#include <math.h>

// ---------------------------------------------------------------------------
// ConvLSTMBlock via ldmatrix + mma.sync (HMMA; harness PTX target sm_103,
// tcgen05 unavailable). Legacy HMMA.F32 ~512 MAC/cyc/SM; GEMMs near that
// roofline.
//   input conv : GEMM M=262144, N=256, K=288 (chunks 64x4 + 32), stride2
//   recurrent  : GEMM M=16384,  N=256, K=576, persistent kernel, 15 steps
// R17: R15 base (passed) + gemm_in K-pad trim (320->288) + fast tanh only.
// R16's barrier restructure reverted (container-kill suspect).
// ---------------------------------------------------------------------------

// ---- device scratch (allocation-free rule) ----
__device__ __align__(1024) __half g_xzh[(size_t)64 * 4096 * 256];
__device__ __align__(1024) __half g_hf2[2][(size_t)4 * 4096 * 64];
__device__ __align__(1024) __half g_xh[(size_t)64 * 128 * 128 * 32];
__device__ __align__(1024) __half g_UH[256 * 576];
__device__ __align__(1024) __half g_WH[256 * 320];
__device__ volatile unsigned g_bar[16];

// ---- PTX helpers ----
__device__ __forceinline__ uint32_t s2u(const void* p) {
    uint32_t a;
    asm("{ .reg .u64 t; cvta.to.shared.u64 t, %1; cvt.u32.u64 %0, t; }"
        : "=r"(a) : "l"(p));
    return a;
}
__device__ __forceinline__ void cpa16(uint32_t dst, const void* src, uint32_t sz) {
    asm volatile("cp.async.cg.shared.global [%0], [%1], 16, %2;"
                 :: "r"(dst), "l"(src), "r"(sz));
}
__device__ __forceinline__ void cpcommit() {
    asm volatile("cp.async.commit_group;" ::: "memory");
}
template <int N> __device__ __forceinline__ void cpwait() {
    asm volatile("cp.async.wait_group %0;" :: "n"(N) : "memory");
}
__device__ __forceinline__ void ldm4(uint32_t* r, uint32_t addr) {
    asm volatile("ldmatrix.sync.aligned.m8n8.x4.shared.b16 {%0,%1,%2,%3}, [%4];"
                 : "=r"(r[0]), "=r"(r[1]), "=r"(r[2]), "=r"(r[3]) : "r"(addr));
}
__device__ __forceinline__ void mma16816(float* d, const uint32_t* a,
                                         uint32_t b0, uint32_t b1) {
    asm volatile(
        "mma.sync.aligned.m16n8k16.row.col.f32.f16.f16.f32 "
        "{%0,%1,%2,%3}, {%4,%5,%6,%7}, {%8,%9}, {%0,%1,%2,%3};"
        : "+f"(d[0]), "+f"(d[1]), "+f"(d[2]), "+f"(d[3])
        : "r"(a[0]), "r"(a[1]), "r"(a[2]), "r"(a[3]), "r"(b0), "r"(b1));
}
__device__ __forceinline__ float ftanh(float x) {
    float e = __expf(2.0f * x);
    return 1.0f - __fdividef(2.0f, e + 1.0f);
}

// ---- prep kernels (as in R15, proven) ----
__global__ void prep_weights(const float* __restrict__ W, const float* __restrict__ U) {
    int idx = blockIdx.x * 256 + threadIdx.x;
    if (idx < 16) *((unsigned*)(g_bar + idx)) = 0u;
    const int NU = 256 * 576;
    if (idx < NU) {
        int n = idx / 576, col = idx - n * 576;
        g_UH[idx] = __float2half_rn(U[(size_t)col * 256 + n]);
    } else {
        int j = idx - NU;
        if (j >= 256 * 320) return;
        int n = j / 320, col = j - n * 320;
        g_WH[j] = __float2half_rn((col < 288) ? W[(size_t)col * 256 + n] : 0.0f);
    }
}

__global__ void x_convert(const float4* __restrict__ x) {
    size_t i = (size_t)blockIdx.x * 256 + threadIdx.x;
    if (i >= (size_t)64 * 128 * 128 * 32 / 8) return;
    float4 v0 = x[2 * i], v1 = x[2 * i + 1];
    __half2 h0 = __floats2half2_rn(v0.x, v0.y);
    __half2 h1 = __floats2half2_rn(v0.z, v0.w);
    __half2 h2 = __floats2half2_rn(v1.x, v1.y);
    __half2 h3 = __floats2half2_rn(v1.z, v1.w);
    uint4 u;
    u.x = *reinterpret_cast<uint32_t*>(&h0);
    u.y = *reinterpret_cast<uint32_t*>(&h1);
    u.z = *reinterpret_cast<uint32_t*>(&h2);
    u.w = *reinterpret_cast<uint32_t*>(&h3);
    reinterpret_cast<uint4*>(g_xh)[i] = u;
}

// ---------------------------------------------------------------------------
// Input conv GEMM. CTA 128 rows x 256 cols, 16 warps (2M x 8N). K chunks:
// 4 full (64) + 1 half (32, real K=288). Single sync per chunk.
// ---------------------------------------------------------------------------
__global__ void __launch_bounds__(512, 1) gemm_in() {
    extern __shared__ char dsm[];
    const uint32_t smA = s2u(dsm);
    const uint32_t smB = smA + 32768;

    const int tid  = threadIdx.x;
    const int warp = tid >> 5;
    const int L    = tid & 31;
    const int tile = blockIdx.x;
    const int wm   = (warp >> 3) * 64;
    const int g8   = (warp & 7) * 8;

    const __half* aBase[2];
    uint32_t aDst[2];
    int aY[2], aX[2], aQh[2];
#pragma unroll
    for (int j = 0; j < 2; j++) {
        int i = tid + j * 512;
        int r = i >> 3, q = i & 7;
        int row = tile * 128 + r;
        int img = row >> 12, px = row & 4095;
        aY[j] = px >> 6; aX[j] = px & 63;
        aQh[j] = q >> 2;
        int ci0 = (q & 3) << 3;
        aBase[j] = g_xh + ((size_t)img << 19) + ci0;
        aDst[j] = (uint32_t)(r * 128 + ((q ^ (r & 7)) << 4));
    }
    const __half* bBase[4];
    uint32_t bDst[4];
#pragma unroll
    for (int j = 0; j < 4; j++) {
        int i = tid + j * 512;
        int n = i >> 3, q = i & 7;
        bBase[j] = g_WH + n * 320 + q * 8;
        bDst[j] = (uint32_t)(n * 128 + ((q ^ (n & 7)) << 4));
    }
    // half-chunk (K=32) B geometry: 1024 16B units over 2 waves
    const __half* bBaseH[2];
    uint32_t bDstH[2];
#pragma unroll
    for (int j = 0; j < 2; j++) {
        int u = tid + j * 512;
        int n = u >> 2, q = u & 3;
        bBaseH[j] = g_WH + n * 320 + 256 + q * 8;
        bDstH[j] = (uint32_t)(n * 128 + ((q ^ (n & 7)) << 4));
    }

    const int sub  = L >> 3;
    const int ri16 = ((sub & 1) << 3) + (L & 7);
    const int us   = sub >> 1;
    uint32_t kksel[4];
#pragma unroll
    for (int kk = 0; kk < 4; kk++) kksel[kk] = (uint32_t)(((kk << 1) | us) << 4);

    uint32_t aRow[4], aRMs[4], bRow[2];
#pragma unroll
    for (int mi = 0; mi < 4; mi++) {
        int r = wm + mi * 16 + ri16;
        aRow[mi] = (uint32_t)(r * 128);
        aRMs[mi] = (uint32_t)((r & 7) << 4);
    }
    uint32_t bRMs = (uint32_t)((L & 7) << 4);
#pragma unroll
    for (int jj = 0; jj < 2; jj++) {
        int n = g8 + jj * 128 + ((sub & 1) << 6) + (L & 7);
        bRow[jj] = (uint32_t)(n * 128);
    }

    float d[4][4][4];
#pragma unroll
    for (int mi = 0; mi < 4; mi++)
#pragma unroll
        for (int n8 = 0; n8 < 4; n8++)
#pragma unroll
            for (int k = 0; k < 4; k++) d[mi][n8][k] = 0.0f;

    auto load_chunk = [&](int c, int s, bool half) {
#pragma unroll
        for (int j = 0; j < 2; j++) {
            int kpos = 2 * c + aQh[j];
            int ky = (kpos >= 6) ? 2 : ((kpos >= 3) ? 1 : 0);
            int kx = kpos - 3 * ky;
            int sy = aY[j] * 2 + ky;
            int sx = aX[j] * 2 + kx;
            bool ok = (kpos < 9) && (sy < 128) && (sx < 128);
            uint32_t off = ok ? (uint32_t)((((sy << 7) + sx) << 5)) : 0u;
            cpa16(smA + (uint32_t)s * 16384u + aDst[j], aBase[j] + off, ok ? 16u : 0u);
        }
        if (!half) {
#pragma unroll
            for (int j = 0; j < 4; j++)
                cpa16(smB + (uint32_t)s * 32768u + bDst[j], bBase[j] + (c << 6), 16u);
        } else {
#pragma unroll
            for (int j = 0; j < 2; j++)
                cpa16(smB + (uint32_t)s * 32768u + bDstH[j], bBaseH[j], 16u);
        }
        cpcommit();
    };

    load_chunk(0, 0, false);

#pragma unroll
    for (int c = 0; c < 5; c++) {
        int s = c & 1;
        cpwait<0>();
        __syncthreads();
        if (c + 1 < 5) load_chunk(c + 1, s ^ 1, (c + 1) == 4);
        uint32_t sa = smA + (uint32_t)s * 16384u;
        uint32_t sb = smB + (uint32_t)s * 32768u;
        const int KKN = (c == 4) ? 2 : 4;
#pragma unroll
        for (int kk = 0; kk < 4; kk++) {
            if (kk >= KKN) break;
            uint32_t a[4][4];
#pragma unroll
            for (int mi = 0; mi < 4; mi++)
                ldm4(a[mi], sa + aRow[mi] + (kksel[kk] ^ aRMs[mi]));
#pragma unroll
            for (int jj = 0; jj < 2; jj++) {
                uint32_t b[4];
                ldm4(b, sb + bRow[jj] + (kksel[kk] ^ bRMs));
#pragma unroll
                for (int mi = 0; mi < 4; mi++) {
                    mma16816(d[mi][2 * jj],     a[mi], b[0], b[2]);
                    mma16816(d[mi][2 * jj + 1], a[mi], b[1], b[3]);
                }
            }
        }
    }

#pragma unroll
    for (int mi = 0; mi < 4; mi++) {
        int r0 = tile * 128 + wm + mi * 16 + (L >> 2);
#pragma unroll
        for (int n8 = 0; n8 < 4; n8++) {
            int col = g8 + n8 * 64 + ((L & 3) << 1);
            *reinterpret_cast<__half2*>(g_xzh + (size_t)r0 * 256 + col) =
                __floats2half2_rn(d[mi][n8][0], d[mi][n8][1]);
            *reinterpret_cast<__half2*>(g_xzh + (size_t)(r0 + 8) * 256 + col) =
                __floats2half2_rn(d[mi][n8][2], d[mi][n8][3]);
        }
    }
}

// ---------------------------------------------------------------------------
// Persistent recurrent kernel: 128 CTAs (one per M-tile), 16 timesteps.
// R15 structure verbatim (passed): grid barrier via gbar lambda, h double-
// buffered, c-state in smem, xz tile in smem, chunk order {3,4,5,0,1,2,6,7,8}
// with chunk3 + xz prefetched before the barrier.
// ---------------------------------------------------------------------------
__global__ void __launch_bounds__(512, 1) rec_loop(
    float* __restrict__ out, const float* __restrict__ bias,
    const float* __restrict__ gamma, const float* __restrict__ beta,
    const float* __restrict__ mean, const float* __restrict__ var)
{
    extern __shared__ char dsm[];
    const uint32_t smA = s2u(dsm);
    const uint32_t smB = smA + 32768;
    float*  c_sm = reinterpret_cast<float*>(dsm + 98304);     // 128*65 floats
    __half* zxs  = reinterpret_cast<__half*>(dsm + 131584);   // 128 x 264 halves
    const uint32_t smXZ = s2u(dsm) + 131584u;

    const int tid  = threadIdx.x;
    const int warp = tid >> 5;
    const int L    = tid & 31;
    const int tile = blockIdx.x;
    const int wm   = (warp >> 3) * 64;
    const int g8   = (warp & 7) * 8;
    const int f0   = g8 + ((L & 3) << 1);

    size_t aOff[2];
    uint32_t aDst[2];
    int aY[2], aX[2];
#pragma unroll
    for (int j = 0; j < 2; j++) {
        int i = tid + j * 512;
        int r = i >> 3, q = i & 7;
        int row = tile * 128 + r;
        int img = row >> 12, px = row & 4095;
        aY[j] = px >> 6; aX[j] = px & 63;
        aOff[j] = ((size_t)img << 18) + (q << 3);
        aDst[j] = (uint32_t)(r * 128 + ((q ^ (r & 7)) << 4));
    }
    const __half* bBase[4];
    uint32_t bDst[4];
#pragma unroll
    for (int j = 0; j < 4; j++) {
        int i = tid + j * 512;
        int n = i >> 3, q = i & 7;
        bBase[j] = g_UH + n * 576 + q * 8;
        bDst[j] = (uint32_t)(n * 128 + ((q ^ (n & 7)) << 4));
    }
    size_t xzOff[8];
    uint32_t xzDst[8];
#pragma unroll
    for (int j = 0; j < 8; j++) {
        int u = tid + j * 512;
        int r = u >> 5, q = u & 31;
        int rg = tile * 128 + r;
        int b_ = rg >> 12, pix = rg & 4095;
        xzOff[j] = ((size_t)b_ << 24) + ((size_t)pix << 8) + (q << 3);
        xzDst[j] = (uint32_t)(r * 528 + q * 16);
    }

    const int sub  = L >> 3;
    const int ri16 = ((sub & 1) << 3) + (L & 7);
    const int us   = sub >> 1;
    uint32_t kksel[4];
#pragma unroll
    for (int kk = 0; kk < 4; kk++) kksel[kk] = (uint32_t)(((kk << 1) | us) << 4);

    uint32_t aRow[4], aRMs[4], bRow[2];
#pragma unroll
    for (int mi = 0; mi < 4; mi++) {
        int r = wm + mi * 16 + ri16;
        aRow[mi] = (uint32_t)(r * 128);
        aRMs[mi] = (uint32_t)((r & 7) << 4);
    }
    uint32_t bRMs = (uint32_t)((L & 7) << 4);
#pragma unroll
    for (int jj = 0; jj < 2; jj++) {
        int n = g8 + jj * 128 + ((sub & 1) << 6) + (L & 7);
        bRow[jj] = (uint32_t)(n * 128);
    }

    float bi[4][2];
#pragma unroll
    for (int g = 0; g < 4; g++) {
        bi[g][0] = bias[g * 64 + f0];
        bi[g][1] = bias[g * 64 + f0 + 1];
    }
    const float sc0 = gamma[f0] * rsqrtf(var[f0] + 1e-3f);
    const float sc1 = gamma[f0 + 1] * rsqrtf(var[f0 + 1] + 1e-3f);
    const float m0 = mean[f0], m1 = mean[f0 + 1];
    const float be0 = beta[f0], be1 = beta[f0 + 1];

    auto load_chunk = [&](const __half* aBuf, int c, int s) {
#pragma unroll
        for (int j = 0; j < 2; j++) {
            int ky = (c >= 6) ? 2 : ((c >= 3) ? 1 : 0);
            int kx = c - 3 * ky;
            int sy = aY[j] + ky - 1;
            int sx = aX[j] + kx - 1;
            bool ok = ((unsigned)sy < 64u) && ((unsigned)sx < 64u);
            uint32_t off = ok ? (uint32_t)((((sy << 6) + sx) << 6)) : 0u;
            cpa16(smA + (uint32_t)s * 16384u + aDst[j],
                  aBuf + aOff[j] + off, ok ? 16u : 0u);
        }
#pragma unroll
        for (int j = 0; j < 4; j++)
            cpa16(smB + (uint32_t)s * 32768u + bDst[j], bBase[j] + (c << 6), 16u);
        cpcommit();
    };
    auto prefetch_xz = [&](int t) {
        size_t tOff = (size_t)t << 20;
#pragma unroll
        for (int j = 0; j < 8; j++)
            cpa16(smXZ + xzDst[j], g_xzh + xzOff[j] + tOff, 16u);
        cpcommit();
    };

    // ---- t = 0 pointwise (h0 = c0 = 0): z = xz + b ; writes h buffer 0 ----
#pragma unroll
    for (int mi = 0; mi < 4; mi++)
#pragma unroll
        for (int h2 = 0; h2 < 2; h2++) {
            int rloc = wm + mi * 16 + (L >> 2) + 8 * h2;
            int rg = tile * 128 + rloc;
            int b_ = rg >> 12, pix = rg & 4095;
            size_t xzb = ((((size_t)b_ * 16) * 4096 + pix) << 8) + f0;
            float2 xi = __half22float2(*(const __half2*)(g_xzh + xzb));
            float2 xg = __half22float2(*(const __half2*)(g_xzh + xzb + 128));
            float2 xo = __half22float2(*(const __half2*)(g_xzh + xzb + 192));
            float ig0 = __saturatef(0.2f * (xi.x + bi[0][0]) + 0.5f);
            float ig1 = __saturatef(0.2f * (xi.y + bi[0][1]) + 0.5f);
            float og0 = __saturatef(0.2f * (xo.x + bi[3][0]) + 0.5f);
            float og1 = __saturatef(0.2f * (xo.y + bi[3][1]) + 0.5f);
            float cn0 = ig0 * ftanh(xg.x + bi[2][0]);
            float cn1 = ig1 * ftanh(xg.y + bi[2][1]);
            float hn0 = og0 * ftanh(cn0);
            float hn1 = og1 * ftanh(cn1);
            c_sm[rloc * 65 + f0] = cn0;
            c_sm[rloc * 65 + f0 + 1] = cn1;
            *reinterpret_cast<__half2*>(g_hf2[0] + (size_t)rg * 64 + f0) =
                __floats2half2_rn(hn0, hn1);
            *reinterpret_cast<float2*>(out + ((((size_t)b_ * 16) * 4096 + pix) << 6) + f0) =
                make_float2((hn0 - m0) * sc0 + be0, (hn1 - m1) * sc1 + be1);
        }

    auto gbar = [&](int i) {
        __threadfence();
        __syncthreads();
        if (tid == 0) {
            atomicAdd((unsigned*)(g_bar + i), 1u);
            while (g_bar[i] < 128u) __nanosleep(64);
        }
        __syncthreads();
    };

    // pre-barrier prefetch for t=1: chunk 3 (own rows) + xz tile
    __syncthreads();
    load_chunk(g_hf2[0], 3, 0);
    prefetch_xz(1);
    gbar(0);

    const int ORD[9] = {3, 4, 5, 0, 1, 2, 6, 7, 8};

#pragma unroll 1
    for (int t = 1; t < 16; t++) {
        const __half* aBuf = g_hf2[(t + 1) & 1];
        __half* hw = g_hf2[t & 1];

        float d[4][4][4];
#pragma unroll
        for (int mi = 0; mi < 4; mi++)
#pragma unroll
            for (int n8 = 0; n8 < 4; n8++)
#pragma unroll
                for (int k = 0; k < 4; k++) d[mi][n8][k] = 0.0f;

#pragma unroll
        for (int i = 0; i < 9; i++) {
            int s = i & 1;
            if (i == 0) cpwait<1>(); else cpwait<0>();
            __syncthreads();
            if (i + 1 < 9) load_chunk(aBuf, ORD[i + 1], (i + 1) & 1);
            uint32_t sa = smA + (uint32_t)s * 16384u;
            uint32_t sb = smB + (uint32_t)s * 32768u;
#pragma unroll
            for (int kk = 0; kk < 4; kk++) {
                uint32_t a[4][4];
#pragma unroll
                for (int mi = 0; mi < 4; mi++)
                    ldm4(a[mi], sa + aRow[mi] + (kksel[kk] ^ aRMs[mi]));
#pragma unroll
                for (int jj = 0; jj < 2; jj++) {
                    uint32_t b[4];
                    ldm4(b, sb + bRow[jj] + (kksel[kk] ^ bRMs));
#pragma unroll
                    for (int mi = 0; mi < 4; mi++) {
                        mma16816(d[mi][2 * jj],     a[mi], b[0], b[2]);
                        mma16816(d[mi][2 * jj + 1], a[mi], b[1], b[3]);
                    }
                }
            }
        }

        // register gate epilogue (xz from smem, conflict-free)
#pragma unroll
        for (int mi = 0; mi < 4; mi++)
#pragma unroll
            for (int h2 = 0; h2 < 2; h2++) {
                int rloc = wm + mi * 16 + (L >> 2) + 8 * h2;
                int rg = tile * 128 + rloc;
                int b_ = rg >> 12, pix = rg & 4095;
                const __half* zr = zxs + rloc * 264 + f0;
                float2 xi = __half22float2(*(const __half2*)(zr));
                float2 xf = __half22float2(*(const __half2*)(zr + 64));
                float2 xg = __half22float2(*(const __half2*)(zr + 128));
                float2 xo = __half22float2(*(const __half2*)(zr + 192));
                int k0 = 2 * h2;
                float zi0 = d[mi][0][k0] + xi.x + bi[0][0];
                float zf0 = d[mi][1][k0] + xf.x + bi[1][0];
                float zg0 = d[mi][2][k0] + xg.x + bi[2][0];
                float zo0 = d[mi][3][k0] + xo.x + bi[3][0];
                float zi1 = d[mi][0][k0 + 1] + xi.y + bi[0][1];
                float zf1 = d[mi][1][k0 + 1] + xf.y + bi[1][1];
                float zg1 = d[mi][2][k0 + 1] + xg.y + bi[2][1];
                float zo1 = d[mi][3][k0 + 1] + xo.y + bi[3][1];
                float ig0 = __saturatef(0.2f * zi0 + 0.5f);
                float fg0 = __saturatef(0.2f * zf0 + 0.5f);
                float og0 = __saturatef(0.2f * zo0 + 0.5f);
                float ig1 = __saturatef(0.2f * zi1 + 0.5f);
                float fg1 = __saturatef(0.2f * zf1 + 0.5f);
                float og1 = __saturatef(0.2f * zo1 + 0.5f);
                int ci = rloc * 65 + f0;
                float cn0 = fg0 * c_sm[ci] + ig0 * ftanh(zg0);
                float cn1 = fg1 * c_sm[ci + 1] + ig1 * ftanh(zg1);
                float hn0 = og0 * ftanh(cn0);
                float hn1 = og1 * ftanh(cn1);
                c_sm[ci] = cn0;
                c_sm[ci + 1] = cn1;
                *reinterpret_cast<__half2*>(hw + (size_t)rg * 64 + f0) =
                    __floats2half2_rn(hn0, hn1);
                *reinterpret_cast<float2*>(
                    out + ((((size_t)b_ * 16 + t) * 4096 + pix) << 6) + f0) =
                    make_float2((hn0 - m0) * sc0 + be0, (hn1 - m1) * sc1 + be1);
            }

        if (t < 15) {
            __syncthreads();              // h writes + zxs reads complete
            load_chunk(hw, 3, 0);         // next step chunk 3 (own rows)
            prefetch_xz(t + 1);
            gbar(t);
        }
    }
}

extern "C" void kernel_launch(void* const* d_in, const int* in_sizes, int n_in,
                              void* d_out, int out_size)
{
    const float* x     = (const float*)d_in[0];
    const float* W     = (const float*)d_in[1];
    const float* U     = (const float*)d_in[2];
    const float* b     = (const float*)d_in[3];
    const float* gamma = (const float*)d_in[4];
    const float* beta  = (const float*)d_in[5];
    const float* mean  = (const float*)d_in[6];
    const float* var   = (const float*)d_in[7];
    float* out = (float*)d_out;

    const int SMEM_IN  = 2 * 16384 + 2 * 32768;                 // 98304 B
    const int SMEM_REC = 98304 + 128 * 65 * 4 + 128 * 264 * 2;  // 199168 B

    cudaFuncSetAttribute((const void*)gemm_in,
                         cudaFuncAttributeMaxDynamicSharedMemorySize, SMEM_IN);
    cudaFuncSetAttribute((const void*)rec_loop,
                         cudaFuncAttributeMaxDynamicSharedMemorySize, SMEM_REC);

    prep_weights<<<896, 256>>>(W, U);
    x_convert<<<32768, 256>>>((const float4*)x);

    gemm_in<<<2048, 512, SMEM_IN>>>();

    rec_loop<<<128, 512, SMEM_REC>>>(out, b, gamma, beta, mean, var);
}